// round 1
// baseline (speedup 1.0000x reference)
#include <cuda_runtime.h>
#include <cstdio>

#define BATCH 4
#define CCH 256
#define HW 4096
#define NQKV 768
#define NGROUPS 16
#define GSIZE 16
#define EPS 1e-5f

// ---------------- scratch (allocation-free: __device__ globals) ----------------
__device__ float g_xn[(size_t)BATCH * CCH * HW];           // 16 MB
__device__ float g_qkv[(size_t)BATCH * NQKV * HW];         // 48 MB
__device__ float g_scores[(size_t)BATCH * HW * HW];        // 256 MB
__device__ float g_attnout[(size_t)BATCH * CCH * HW];      // 16 MB
__device__ float g_mean[BATCH * NGROUPS];
__device__ float g_rstd[BATCH * NGROUPS];

// ---------------- GroupNorm stats: one block per (b, g) ----------------
__global__ void gn_stats(const float* __restrict__ x) {
    int bg = blockIdx.x;  // 0..63
    const float4* p = (const float4*)(x + (size_t)bg * GSIZE * HW);  // 65536 floats contiguous
    float s = 0.f, sq = 0.f;
    for (int i = threadIdx.x; i < 16384; i += 256) {
        float4 v = p[i];
        s  += v.x + v.y + v.z + v.w;
        sq += v.x*v.x + v.y*v.y + v.z*v.z + v.w*v.w;
    }
    __shared__ float ss[256], sz[256];
    ss[threadIdx.x] = s; sz[threadIdx.x] = sq;
    __syncthreads();
    for (int o = 128; o > 0; o >>= 1) {
        if (threadIdx.x < o) { ss[threadIdx.x] += ss[threadIdx.x + o]; sz[threadIdx.x] += sz[threadIdx.x + o]; }
        __syncthreads();
    }
    if (threadIdx.x == 0) {
        float m = ss[0] * (1.f / 65536.f);
        float v = sz[0] * (1.f / 65536.f) - m * m;
        g_mean[bg] = m;
        g_rstd[bg] = rsqrtf(v + EPS);
    }
}

// ---------------- GroupNorm apply (elementwise, vectorized) ----------------
__global__ void gn_apply(const float* __restrict__ x, const float* __restrict__ w,
                         const float* __restrict__ bgn) {
    int i4 = blockIdx.x * 256 + threadIdx.x;       // 1M float4s total
    int rowc = i4 >> 10;                           // (b*256 + c), since 4096 floats per channel
    int c = rowc & 255;
    int bg = (rowc >> 8) * NGROUPS + (c >> 4);
    float m = g_mean[bg], rs = g_rstd[bg];
    float sc = rs * w[c];
    float sh = bgn[c] - m * sc;
    float4 v = ((const float4*)x)[i4];
    float4 o;
    o.x = v.x * sc + sh; o.y = v.y * sc + sh; o.z = v.z * sc + sh; o.w = v.w * sc + sh;
    ((float4*)g_xn)[i4] = o;
}

// ---------------- Generic tiled SGEMM ----------------
// C[b][m][n] = alpha * sum_k opA(A)[m,k] * opB(B)[k,n]  (+ bias[m]) (+ resid[b][m][n])
// AMODE 0: A[m][k], lda=K.  AMODE 1: A[k][m], lda=M.
// BMODE 0: B[k][n], ldb=N.  BMODE 1: B[n][k], ldb=K.
#define BM 128
#define BN 128
#define BK 8

template <int AMODE, int BMODE, bool BIAS, bool RES>
__global__ __launch_bounds__(256, 2)
void gemm_kernel(const float* __restrict__ A, const float* __restrict__ B,
                 float* __restrict__ Cc, const float* __restrict__ bias,
                 const float* __restrict__ resid,
                 int M, int N, int K, float alpha,
                 size_t sA, size_t sB, size_t sC, size_t sR) {
    __shared__ float As[BK][BM];
    __shared__ float Bs[BK][BN];

    int b = blockIdx.z;
    A += (size_t)b * sA;
    B += (size_t)b * sB;
    Cc += (size_t)b * sC;
    const float* Rp = RES ? (resid + (size_t)b * sR) : nullptr;

    int bm = blockIdx.y * BM;
    int bn = blockIdx.x * BN;
    int tid = threadIdx.x;        // 256 threads = 16x16
    int tr = tid >> 4;            // thread row 0..15 (owns 8 m-rows)
    int tc = tid & 15;            // thread col 0..15 (owns 8 n-cols)

    float acc[8][8];
    #pragma unroll
    for (int i = 0; i < 8; i++)
        #pragma unroll
        for (int j = 0; j < 8; j++) acc[i][j] = 0.f;

    for (int k0 = 0; k0 < K; k0 += BK) {
        // ---- load A tile into As[k][m] ----
        if (AMODE == 0) {
            int row = tid >> 1, ks = (tid & 1) * 4;
            float4 v = *(const float4*)&A[(size_t)(bm + row) * K + k0 + ks];
            As[ks + 0][row] = v.x; As[ks + 1][row] = v.y;
            As[ks + 2][row] = v.z; As[ks + 3][row] = v.w;
        } else {
            int kk = tid >> 5, m4 = (tid & 31) * 4;
            *(float4*)&As[kk][m4] = *(const float4*)&A[(size_t)(k0 + kk) * M + bm + m4];
        }
        // ---- load B tile into Bs[k][n] ----
        if (BMODE == 0) {
            int kk = tid >> 5, n4 = (tid & 31) * 4;
            *(float4*)&Bs[kk][n4] = *(const float4*)&B[(size_t)(k0 + kk) * N + bn + n4];
        } else {
            int row = tid >> 1, ks = (tid & 1) * 4;
            float4 v = *(const float4*)&B[(size_t)(bn + row) * K + k0 + ks];
            Bs[ks + 0][row] = v.x; Bs[ks + 1][row] = v.y;
            Bs[ks + 2][row] = v.z; Bs[ks + 3][row] = v.w;
        }
        __syncthreads();

        #pragma unroll
        for (int kk = 0; kk < BK; kk++) {
            float a[8], bb[8];
            *(float4*)&a[0]  = *(const float4*)&As[kk][tr * 8];
            *(float4*)&a[4]  = *(const float4*)&As[kk][tr * 8 + 4];
            *(float4*)&bb[0] = *(const float4*)&Bs[kk][tc * 8];
            *(float4*)&bb[4] = *(const float4*)&Bs[kk][tc * 8 + 4];
            #pragma unroll
            for (int i = 0; i < 8; i++)
                #pragma unroll
                for (int j = 0; j < 8; j++)
                    acc[i][j] += a[i] * bb[j];
        }
        __syncthreads();
    }

    // ---- epilogue ----
    #pragma unroll
    for (int i = 0; i < 8; i++) {
        size_t row = bm + tr * 8 + i;
        float bv = BIAS ? bias[row] : 0.f;
        float* cp = &Cc[row * (size_t)N + bn + tc * 8];
        const float* rp = RES ? &Rp[row * (size_t)N + bn + tc * 8] : nullptr;
        #pragma unroll
        for (int j = 0; j < 8; j += 4) {
            float4 v;
            v.x = acc[i][j + 0] * alpha + bv;
            v.y = acc[i][j + 1] * alpha + bv;
            v.z = acc[i][j + 2] * alpha + bv;
            v.w = acc[i][j + 3] * alpha + bv;
            if (RES) {
                float4 r = *(const float4*)&rp[j];
                v.x += r.x; v.y += r.y; v.z += r.z; v.w += r.w;
            }
            *(float4*)&cp[j] = v;
        }
    }
}

// ---------------- row softmax over scores ----------------
__global__ void softmax_rows() {
    size_t row = blockIdx.x;  // 0..16383
    float4* p4 = (float4*)(g_scores + row * (size_t)HW);
    float4 v[4];
    float mx = -1e30f;
    #pragma unroll
    for (int j = 0; j < 4; j++) {
        v[j] = p4[threadIdx.x + j * 256];
        mx = fmaxf(mx, fmaxf(fmaxf(v[j].x, v[j].y), fmaxf(v[j].z, v[j].w)));
    }
    __shared__ float sm[256];
    sm[threadIdx.x] = mx;
    __syncthreads();
    for (int o = 128; o > 0; o >>= 1) {
        if (threadIdx.x < o) sm[threadIdx.x] = fmaxf(sm[threadIdx.x], sm[threadIdx.x + o]);
        __syncthreads();
    }
    mx = sm[0];
    __syncthreads();
    float s = 0.f;
    #pragma unroll
    for (int j = 0; j < 4; j++) {
        v[j].x = __expf(v[j].x - mx); v[j].y = __expf(v[j].y - mx);
        v[j].z = __expf(v[j].z - mx); v[j].w = __expf(v[j].w - mx);
        s += v[j].x + v[j].y + v[j].z + v[j].w;
    }
    sm[threadIdx.x] = s;
    __syncthreads();
    for (int o = 128; o > 0; o >>= 1) {
        if (threadIdx.x < o) sm[threadIdx.x] += sm[threadIdx.x + o];
        __syncthreads();
    }
    float inv = 1.f / sm[0];
    #pragma unroll
    for (int j = 0; j < 4; j++) {
        v[j].x *= inv; v[j].y *= inv; v[j].z *= inv; v[j].w *= inv;
        p4[threadIdx.x + j * 256] = v[j];
    }
}

// ---------------- launch ----------------
extern "C" void kernel_launch(void* const* d_in, const int* in_sizes, int n_in,
                              void* d_out, int out_size) {
    const float* x     = (const float*)d_in[0];
    const float* gnw   = (const float*)d_in[1];
    const float* gnb   = (const float*)d_in[2];
    const float* qkvw  = (const float*)d_in[3];
    const float* qkvb  = (const float*)d_in[4];
    const float* projw = (const float*)d_in[5];
    const float* projb = (const float*)d_in[6];
    float* out = (float*)d_out;

    float *xn, *qkv, *scores, *attnout;
    cudaGetSymbolAddress((void**)&xn, g_xn);
    cudaGetSymbolAddress((void**)&qkv, g_qkv);
    cudaGetSymbolAddress((void**)&scores, g_scores);
    cudaGetSymbolAddress((void**)&attnout, g_attnout);

    const size_t sXN  = (size_t)CCH * HW;       // 1048576
    const size_t sQKV = (size_t)NQKV * HW;      // 3145728
    const size_t sSC  = (size_t)HW * HW;        // 16777216

    // 1. GroupNorm
    gn_stats<<<BATCH * NGROUPS, 256>>>(x);
    gn_apply<<<(BATCH * CCH * HW) / (256 * 4), 256>>>(x, gnw, gnb);

    // 2. QKV = W_qkv @ xn + b : M=768, N=4096, K=256 (A shared across batch)
    gemm_kernel<0, 0, true, false><<<dim3(HW / BN, NQKV / BM, BATCH), 256>>>(
        qkvw, xn, qkv, qkvb, nullptr, NQKV, HW, CCH, 1.f, 0, sXN, sQKV, 0);

    // 3. scores = (1/16) * Q^T K : M=4096, N=4096, K=256 ; Q=[c][q], K=[c][k]
    gemm_kernel<1, 0, false, false><<<dim3(HW / BN, HW / BM, BATCH), 256>>>(
        qkv, qkv + (size_t)CCH * HW, scores, nullptr, nullptr,
        HW, HW, CCH, 0.0625f, sQKV, sQKV, sSC, 0);

    // 4. softmax over last dim
    softmax_rows<<<BATCH * HW, 256>>>();

    // 5. attnout[c][q] = sum_k V[c][k] * P[q][k] : M=256, N=4096, K=4096
    gemm_kernel<0, 1, false, false><<<dim3(HW / BN, CCH / BM, BATCH), 256>>>(
        qkv + (size_t)2 * CCH * HW, scores, attnout, nullptr, nullptr,
        CCH, HW, HW, 1.f, sQKV, sSC, sXN, 0);

    // 6. out = x + W_proj @ attnout + b : M=256, N=4096, K=256
    gemm_kernel<0, 0, true, true><<<dim3(HW / BN, CCH / BM, BATCH), 256>>>(
        projw, attnout, out, projb, x, CCH, HW, CCH, 1.f, 0, sXN, sXN, sXN);
}

// round 3
// speedup vs baseline: 1.7678x; 1.7678x over previous
#include <cuda_runtime.h>
#include <cuda_bf16.h>
#include <cstdint>

#define BATCH 4
#define CCH 256
#define HW 4096
#define NQKV 768
#define NGROUPS 16
#define EPS 1e-5f

// ---------------- scratch (__device__ globals; allocation-free) ----------------
__device__ float g_xn[(size_t)BATCH * CCH * HW];            // 16 MB
__device__ float g_qkv[(size_t)BATCH * NQKV * HW];          // 48 MB
__device__ float g_scores[(size_t)BATCH * HW * HW];         // 256 MB
__device__ float g_attnout[(size_t)BATCH * HW * CCH];       // 16 MB, [b][n][c]
__device__ float g_mean[BATCH * NGROUPS];
__device__ float g_rstd[BATCH * NGROUPS];
// bf16 split operands
__device__ __nv_bfloat16 g_qh[(size_t)BATCH * HW * CCH];    // [b][n][c]
__device__ __nv_bfloat16 g_ql[(size_t)BATCH * HW * CCH];
__device__ __nv_bfloat16 g_kh[(size_t)BATCH * HW * CCH];    // [b][n][c]
__device__ __nv_bfloat16 g_kl[(size_t)BATCH * HW * CCH];
__device__ __nv_bfloat16 g_vh[(size_t)BATCH * CCH * HW];    // [b][c][n]
__device__ __nv_bfloat16 g_vl[(size_t)BATCH * CCH * HW];
__device__ __nv_bfloat16 g_ph[(size_t)BATCH * HW * HW];     // [b][q][k]  128 MB
__device__ __nv_bfloat16 g_pl[(size_t)BATCH * HW * HW];     // 128 MB

// ---------------- helpers ----------------
__device__ __forceinline__ uint32_t smem_u32(const void* p) {
    uint32_t a;
    asm("{ .reg .u64 t; cvta.to.shared.u64 t, %1; cvt.u32.u64 %0, t; }" : "=r"(a) : "l"(p));
    return a;
}
__device__ __forceinline__ void cp16(uint32_t s, const void* g) {
    asm volatile("cp.async.cg.shared.global [%0], [%1], 16;" :: "r"(s), "l"(g) : "memory");
}
__device__ __forceinline__ void ldsm4(uint32_t& r0, uint32_t& r1, uint32_t& r2, uint32_t& r3,
                                      uint32_t a) {
    asm volatile("ldmatrix.sync.aligned.m8n8.x4.shared.b16 {%0,%1,%2,%3}, [%4];"
                 : "=r"(r0), "=r"(r1), "=r"(r2), "=r"(r3) : "r"(a));
}
__device__ __forceinline__ void mma_bf16(float* c, const uint32_t* a, const uint32_t* b) {
    asm volatile(
        "mma.sync.aligned.m16n8k16.row.col.f32.bf16.bf16.f32 "
        "{%0,%1,%2,%3}, {%4,%5,%6,%7}, {%8,%9}, {%0,%1,%2,%3};"
        : "+f"(c[0]), "+f"(c[1]), "+f"(c[2]), "+f"(c[3])
        : "r"(a[0]), "r"(a[1]), "r"(a[2]), "r"(a[3]), "r"(b[0]), "r"(b[1]));
}

// ---------------- GroupNorm ----------------
__global__ void gn_stats(const float* __restrict__ x) {
    int bg = blockIdx.x;
    const float4* p = (const float4*)(x + (size_t)bg * 16 * HW);
    float s = 0.f, sq = 0.f;
    for (int i = threadIdx.x; i < 16384; i += 256) {
        float4 v = p[i];
        s  += v.x + v.y + v.z + v.w;
        sq += v.x*v.x + v.y*v.y + v.z*v.z + v.w*v.w;
    }
    __shared__ float ss[256], sz[256];
    ss[threadIdx.x] = s; sz[threadIdx.x] = sq;
    __syncthreads();
    for (int o = 128; o > 0; o >>= 1) {
        if (threadIdx.x < o) { ss[threadIdx.x] += ss[threadIdx.x + o]; sz[threadIdx.x] += sz[threadIdx.x + o]; }
        __syncthreads();
    }
    if (threadIdx.x == 0) {
        float m = ss[0] * (1.f / 65536.f);
        float v = sz[0] * (1.f / 65536.f) - m * m;
        g_mean[bg] = m;
        g_rstd[bg] = rsqrtf(v + EPS);
    }
}

__global__ void gn_apply(const float* __restrict__ x, const float* __restrict__ w,
                         const float* __restrict__ bgn) {
    int i4 = blockIdx.x * 256 + threadIdx.x;
    int rowc = i4 >> 10;
    int c = rowc & 255;
    int bg = (rowc >> 8) * NGROUPS + (c >> 4);
    float m = g_mean[bg], rs = g_rstd[bg];
    float sc = rs * w[c];
    float sh = bgn[c] - m * sc;
    float4 v = ((const float4*)x)[i4];
    float4 o;
    o.x = v.x * sc + sh; o.y = v.y * sc + sh; o.z = v.z * sc + sh; o.w = v.w * sc + sh;
    ((float4*)g_xn)[i4] = o;
}

// ---------------- FFMA tiled SGEMM (qkv, proj) ----------------
#define BM 128
#define BN 128
#define BK 8
template <int AMODE, int BMODE, bool BIAS, bool RES>
__global__ __launch_bounds__(256, 2)
void gemm_kernel(const float* __restrict__ A, const float* __restrict__ B,
                 float* __restrict__ Cc, const float* __restrict__ bias,
                 const float* __restrict__ resid,
                 int M, int N, int K, float alpha,
                 size_t sA, size_t sB, size_t sC, size_t sR) {
    __shared__ float As[BK][BM];
    __shared__ float Bs[BK][BN];
    int b = blockIdx.z;
    A += (size_t)b * sA; B += (size_t)b * sB; Cc += (size_t)b * sC;
    const float* Rp = RES ? (resid + (size_t)b * sR) : nullptr;
    int bm = blockIdx.y * BM, bn = blockIdx.x * BN;
    int tid = threadIdx.x, tr = tid >> 4, tc = tid & 15;
    float acc[8][8];
    #pragma unroll
    for (int i = 0; i < 8; i++)
        #pragma unroll
        for (int j = 0; j < 8; j++) acc[i][j] = 0.f;
    for (int k0 = 0; k0 < K; k0 += BK) {
        if (AMODE == 0) {
            int row = tid >> 1, ks = (tid & 1) * 4;
            float4 v = *(const float4*)&A[(size_t)(bm + row) * K + k0 + ks];
            As[ks + 0][row] = v.x; As[ks + 1][row] = v.y;
            As[ks + 2][row] = v.z; As[ks + 3][row] = v.w;
        } else {
            int kk = tid >> 5, m4 = (tid & 31) * 4;
            *(float4*)&As[kk][m4] = *(const float4*)&A[(size_t)(k0 + kk) * M + bm + m4];
        }
        if (BMODE == 0) {
            int kk = tid >> 5, n4 = (tid & 31) * 4;
            *(float4*)&Bs[kk][n4] = *(const float4*)&B[(size_t)(k0 + kk) * N + bn + n4];
        } else {
            int row = tid >> 1, ks = (tid & 1) * 4;
            float4 v = *(const float4*)&B[(size_t)(bn + row) * K + k0 + ks];
            Bs[ks + 0][row] = v.x; Bs[ks + 1][row] = v.y;
            Bs[ks + 2][row] = v.z; Bs[ks + 3][row] = v.w;
        }
        __syncthreads();
        #pragma unroll
        for (int kk = 0; kk < BK; kk++) {
            float a[8], bb[8];
            *(float4*)&a[0]  = *(const float4*)&As[kk][tr * 8];
            *(float4*)&a[4]  = *(const float4*)&As[kk][tr * 8 + 4];
            *(float4*)&bb[0] = *(const float4*)&Bs[kk][tc * 8];
            *(float4*)&bb[4] = *(const float4*)&Bs[kk][tc * 8 + 4];
            #pragma unroll
            for (int i = 0; i < 8; i++)
                #pragma unroll
                for (int j = 0; j < 8; j++)
                    acc[i][j] += a[i] * bb[j];
        }
        __syncthreads();
    }
    #pragma unroll
    for (int i = 0; i < 8; i++) {
        size_t row = bm + tr * 8 + i;
        float bv = BIAS ? bias[row] : 0.f;
        float* cp = &Cc[row * (size_t)N + bn + tc * 8];
        const float* rp = RES ? &Rp[row * (size_t)N + bn + tc * 8] : nullptr;
        #pragma unroll
        for (int j = 0; j < 8; j += 4) {
            float4 v;
            v.x = acc[i][j + 0] * alpha + bv;
            v.y = acc[i][j + 1] * alpha + bv;
            v.z = acc[i][j + 2] * alpha + bv;
            v.w = acc[i][j + 3] * alpha + bv;
            if (RES) {
                float4 r = *(const float4*)&rp[j];
                v.x += r.x; v.y += r.y; v.z += r.z; v.w += r.w;
            }
            *(float4*)&cp[j] = v;
        }
    }
}

// ---------------- Q/K transpose + bf16 split: [c][n] fp32 -> [n][c] bf16 h/l ----------------
__global__ void qk_transpose_split(const float* __restrict__ qkv) {
    __shared__ float t[32][33];
    int b = blockIdx.z >> 1;
    int which = blockIdx.z & 1;
    const float* src = qkv + (size_t)b * NQKV * HW + (size_t)which * CCH * HW;
    int n0 = blockIdx.x * 32, c0 = blockIdx.y * 32;
    int tx = threadIdx.x, ty = threadIdx.y;
    #pragma unroll
    for (int j = 0; j < 4; j++)
        t[ty + j * 8][tx] = src[(size_t)(c0 + ty + j * 8) * HW + n0 + tx];
    __syncthreads();
    __nv_bfloat16* dh = (which ? g_kh : g_qh) + (size_t)b * HW * CCH;
    __nv_bfloat16* dl = (which ? g_kl : g_ql) + (size_t)b * HW * CCH;
    #pragma unroll
    for (int j = 0; j < 4; j++) {
        float v = t[tx][ty + j * 8];
        __nv_bfloat16 h = __float2bfloat16_rn(v);
        __nv_bfloat16 l = __float2bfloat16_rn(v - __bfloat162float(h));
        size_t o = (size_t)(n0 + ty + j * 8) * CCH + c0 + tx;
        dh[o] = h; dl[o] = l;
    }
}

// ---------------- V bf16 split (no transpose): [c][n] ----------------
__global__ void v_split(const float* __restrict__ qkv) {
    size_t i4 = (size_t)blockIdx.x * 256 + threadIdx.x;
    int b = (int)(i4 >> 18);
    size_t r4 = i4 & 0x3FFFF;
    float4 v = *(const float4*)(qkv + (size_t)b * NQKV * HW + (size_t)2 * CCH * HW + r4 * 4);
    size_t o = (size_t)b * CCH * HW + r4 * 4;
    float f[4] = {v.x, v.y, v.z, v.w};
    __nv_bfloat16 hh[4], ll[4];
    #pragma unroll
    for (int i = 0; i < 4; i++) {
        hh[i] = __float2bfloat16_rn(f[i]);
        ll[i] = __float2bfloat16_rn(f[i] - __bfloat162float(hh[i]));
    }
    *(__nv_bfloat162*)(g_vh + o)     = __nv_bfloat162(hh[0], hh[1]);
    *(__nv_bfloat162*)(g_vh + o + 2) = __nv_bfloat162(hh[2], hh[3]);
    *(__nv_bfloat162*)(g_vl + o)     = __nv_bfloat162(ll[0], ll[1]);
    *(__nv_bfloat162*)(g_vl + o + 2) = __nv_bfloat162(ll[2], ll[3]);
}

// ---------------- softmax: fp32 scores -> bf16 h/l probabilities ----------------
__global__ void softmax_split() {
    size_t row = blockIdx.x;
    const float4* p4 = (const float4*)(g_scores + row * (size_t)HW);
    float4 v[4];
    float mx = -1e30f;
    #pragma unroll
    for (int j = 0; j < 4; j++) {
        v[j] = p4[threadIdx.x + j * 256];
        mx = fmaxf(mx, fmaxf(fmaxf(v[j].x, v[j].y), fmaxf(v[j].z, v[j].w)));
    }
    __shared__ float sm[256];
    sm[threadIdx.x] = mx;
    __syncthreads();
    for (int o = 128; o > 0; o >>= 1) {
        if (threadIdx.x < o) sm[threadIdx.x] = fmaxf(sm[threadIdx.x], sm[threadIdx.x + o]);
        __syncthreads();
    }
    mx = sm[0];
    __syncthreads();
    float s = 0.f;
    #pragma unroll
    for (int j = 0; j < 4; j++) {
        v[j].x = __expf(v[j].x - mx); v[j].y = __expf(v[j].y - mx);
        v[j].z = __expf(v[j].z - mx); v[j].w = __expf(v[j].w - mx);
        s += v[j].x + v[j].y + v[j].z + v[j].w;
    }
    sm[threadIdx.x] = s;
    __syncthreads();
    for (int o = 128; o > 0; o >>= 1) {
        if (threadIdx.x < o) sm[threadIdx.x] += sm[threadIdx.x + o];
        __syncthreads();
    }
    float inv = 1.f / sm[0];
    __nv_bfloat16* oh = g_ph + row * (size_t)HW;
    __nv_bfloat16* ol = g_pl + row * (size_t)HW;
    #pragma unroll
    for (int j = 0; j < 4; j++) {
        float f[4] = {v[j].x * inv, v[j].y * inv, v[j].z * inv, v[j].w * inv};
        __nv_bfloat16 hh[4], ll[4];
        #pragma unroll
        for (int i = 0; i < 4; i++) {
            hh[i] = __float2bfloat16_rn(f[i]);
            ll[i] = __float2bfloat16_rn(f[i] - __bfloat162float(hh[i]));
        }
        size_t o = (size_t)(threadIdx.x + j * 256) * 4;
        *(__nv_bfloat162*)(oh + o)     = __nv_bfloat162(hh[0], hh[1]);
        *(__nv_bfloat162*)(oh + o + 2) = __nv_bfloat162(hh[2], hh[3]);
        *(__nv_bfloat162*)(ol + o)     = __nv_bfloat162(ll[0], ll[1]);
        *(__nv_bfloat162*)(ol + o + 2) = __nv_bfloat162(ll[2], ll[3]);
    }
}

// ---------------- HMMA bf16x3 GEMM: C[128x128] = (Ah+Al).(Bh+Bl)^T ----------------
// A: [m][K] bf16 row-major (stride ASTRIDE), B: [n][K] bf16 row-major (stride BSTRIDE).
// out fp32 (stride OSTRIDE) = alpha * D. K consumed in steps of 32, cp.async double buffer.
// SMEM stage: 4 tiles (Ah, Al, Bh, Bl), each 128 rows x 32 bf16, row stride 80B (pad).
#define TILE_B 10240
#define STAGE_B 40960
#define HMMA_SMEM (2 * STAGE_B)

template<int ASTRIDE, int BSTRIDE, int OSTRIDE>
__global__ __launch_bounds__(256, 1)
void hmma_gemm(const __nv_bfloat16* __restrict__ Ah_, const __nv_bfloat16* __restrict__ Al_,
               const __nv_bfloat16* __restrict__ Bh_, const __nv_bfloat16* __restrict__ Bl_,
               float* __restrict__ out, float alpha, int ksteps,
               size_t aB, size_t bB, size_t oB) {
    extern __shared__ char smem[];
    const uint32_t sb = smem_u32(smem);
    const int tid = threadIdx.x;
    const int wid = tid >> 5, lane = tid & 31;
    const int b = blockIdx.z;
    const int bm = blockIdx.y * 128;
    const int bn = blockIdx.x * 128;
    const int wm = wid & 1, wn = wid >> 1;   // warp covers rows [wm*64, +64), cols [wn*32, +32)

    const __nv_bfloat16* Ah = Ah_ + (size_t)b * aB + (size_t)bm * ASTRIDE;
    const __nv_bfloat16* Al = Al_ + (size_t)b * aB + (size_t)bm * ASTRIDE;
    const __nv_bfloat16* Bh = Bh_ + (size_t)b * bB + (size_t)bn * BSTRIDE;
    const __nv_bfloat16* Bl = Bl_ + (size_t)b * bB + (size_t)bn * BSTRIDE;

    // per-thread gmem->smem chunk coords (2 chunks of 16B per tile per thread)
    const int u0row = tid >> 2, u0c = tid & 3;
    const int u1row = (tid + 256) >> 2, u1c = (tid + 256) & 3;

    float acc[4][4][4];
    #pragma unroll
    for (int mi = 0; mi < 4; mi++)
        #pragma unroll
        for (int ni = 0; ni < 4; ni++)
            #pragma unroll
            for (int r = 0; r < 4; r++) acc[mi][ni][r] = 0.f;

    // ldmatrix lane geometry
    const int g = lane >> 3;
    const int lrow = (g & 1) * 8 + (lane & 7);
    const int lkb  = (g >> 1) * 16;

    auto load_stage = [&](int ks, int buf) {
        const uint32_t base = sb + buf * STAGE_B;
        const int k0 = ks * 32;
        uint32_t so0 = base + u0row * 80 + u0c * 16;
        uint32_t so1 = base + u1row * 80 + u1c * 16;
        size_t ga0 = (size_t)u0row * ASTRIDE + k0 + u0c * 8;
        size_t ga1 = (size_t)u1row * ASTRIDE + k0 + u1c * 8;
        size_t gb0 = (size_t)u0row * BSTRIDE + k0 + u0c * 8;
        size_t gb1 = (size_t)u1row * BSTRIDE + k0 + u1c * 8;
        cp16(so0,              Ah + ga0);
        cp16(so1,              Ah + ga1);
        cp16(so0 + TILE_B,     Al + ga0);
        cp16(so1 + TILE_B,     Al + ga1);
        cp16(so0 + 2 * TILE_B, Bh + gb0);
        cp16(so1 + 2 * TILE_B, Bh + gb1);
        cp16(so0 + 3 * TILE_B, Bl + gb0);
        cp16(so1 + 3 * TILE_B, Bl + gb1);
    };

    load_stage(0, 0);
    asm volatile("cp.async.commit_group;" ::: "memory");

    for (int ks = 0; ks < ksteps; ks++) {
        const int buf = ks & 1;
        if (ks + 1 < ksteps) {
            load_stage(ks + 1, buf ^ 1);
            asm volatile("cp.async.commit_group;" ::: "memory");
            asm volatile("cp.async.wait_group 1;" ::: "memory");
        } else {
            asm volatile("cp.async.wait_group 0;" ::: "memory");
        }
        __syncthreads();

        const uint32_t base = sb + buf * STAGE_B;
        #pragma unroll
        for (int k16 = 0; k16 < 2; k16++) {
            uint32_t ah[4][4], al[4][4], bh[4][2], bl[4][2];
            #pragma unroll
            for (int mi = 0; mi < 4; mi++) {
                uint32_t ra = base + (wm * 64 + mi * 16 + lrow) * 80 + k16 * 32 + lkb;
                ldsm4(ah[mi][0], ah[mi][1], ah[mi][2], ah[mi][3], ra);
                ldsm4(al[mi][0], al[mi][1], al[mi][2], al[mi][3], ra + TILE_B);
            }
            #pragma unroll
            for (int p = 0; p < 2; p++) {
                uint32_t rb = base + 2 * TILE_B + (wn * 32 + p * 16 + lrow) * 80 + k16 * 32 + lkb;
                uint32_t r0, r1, r2, r3;
                ldsm4(r0, r1, r2, r3, rb);
                bh[2*p][0] = r0; bh[2*p+1][0] = r1; bh[2*p][1] = r2; bh[2*p+1][1] = r3;
                ldsm4(r0, r1, r2, r3, rb + TILE_B);
                bl[2*p][0] = r0; bl[2*p+1][0] = r1; bl[2*p][1] = r2; bl[2*p+1][1] = r3;
            }
            #pragma unroll
            for (int mi = 0; mi < 4; mi++)
                #pragma unroll
                for (int ni = 0; ni < 4; ni++) {
                    mma_bf16(acc[mi][ni], ah[mi], bh[ni]);
                    mma_bf16(acc[mi][ni], ah[mi], bl[ni]);
                    mma_bf16(acc[mi][ni], al[mi], bh[ni]);
                }
        }
        __syncthreads();
    }

    // epilogue
    float* outb = out + (size_t)b * oB;
    #pragma unroll
    for (int mi = 0; mi < 4; mi++) {
        int r0 = bm + wm * 64 + mi * 16 + (lane >> 2);
        #pragma unroll
        for (int ni = 0; ni < 4; ni++) {
            int col = bn + wn * 32 + ni * 8 + (lane & 3) * 2;
            float2 v0 = make_float2(acc[mi][ni][0] * alpha, acc[mi][ni][1] * alpha);
            float2 v1 = make_float2(acc[mi][ni][2] * alpha, acc[mi][ni][3] * alpha);
            *(float2*)&outb[(size_t)r0 * OSTRIDE + col] = v0;
            *(float2*)&outb[(size_t)(r0 + 8) * OSTRIDE + col] = v1;
        }
    }
}

// ---------------- launch ----------------
extern "C" void kernel_launch(void* const* d_in, const int* in_sizes, int n_in,
                              void* d_out, int out_size) {
    const float* x     = (const float*)d_in[0];
    const float* gnw   = (const float*)d_in[1];
    const float* gnb   = (const float*)d_in[2];
    const float* qkvw  = (const float*)d_in[3];
    const float* qkvb  = (const float*)d_in[4];
    const float* projw = (const float*)d_in[5];
    const float* projb = (const float*)d_in[6];
    float* out = (float*)d_out;

    float *xn, *qkv, *scores, *attnout;
    __nv_bfloat16 *qh, *ql, *kh, *kl, *vh, *vl, *phh, *pll;
    cudaGetSymbolAddress((void**)&xn, g_xn);
    cudaGetSymbolAddress((void**)&qkv, g_qkv);
    cudaGetSymbolAddress((void**)&scores, g_scores);
    cudaGetSymbolAddress((void**)&attnout, g_attnout);
    cudaGetSymbolAddress((void**)&qh, g_qh);
    cudaGetSymbolAddress((void**)&ql, g_ql);
    cudaGetSymbolAddress((void**)&kh, g_kh);
    cudaGetSymbolAddress((void**)&kl, g_kl);
    cudaGetSymbolAddress((void**)&vh, g_vh);
    cudaGetSymbolAddress((void**)&vl, g_vl);
    cudaGetSymbolAddress((void**)&phh, g_ph);
    cudaGetSymbolAddress((void**)&pll, g_pl);

    const size_t sXN  = (size_t)CCH * HW;
    const size_t sQKV = (size_t)NQKV * HW;
    const size_t sSC  = (size_t)HW * HW;
    const size_t sNC  = (size_t)HW * CCH;

    cudaFuncSetAttribute((const void*)hmma_gemm<CCH, CCH, HW>,
                         cudaFuncAttributeMaxDynamicSharedMemorySize, HMMA_SMEM);
    cudaFuncSetAttribute((const void*)hmma_gemm<HW, HW, CCH>,
                         cudaFuncAttributeMaxDynamicSharedMemorySize, HMMA_SMEM);

    // 1. GroupNorm
    gn_stats<<<BATCH * NGROUPS, 256>>>(x);
    gn_apply<<<(BATCH * CCH * HW) / (256 * 4), 256>>>(x, gnw, gnb);

    // 2. QKV = W_qkv @ xn + b  (FFMA): M=768, N=4096, K=256
    gemm_kernel<0, 0, true, false><<<dim3(HW / BN, NQKV / BM, BATCH), 256>>>(
        qkvw, xn, qkv, qkvb, nullptr, NQKV, HW, CCH, 1.f, 0, sXN, sQKV, 0);

    // 3. split/transposed bf16 operands
    qk_transpose_split<<<dim3(HW / 32, CCH / 32, BATCH * 2), dim3(32, 8)>>>(qkv);
    v_split<<<(BATCH * CCH * HW) / (256 * 4), 256>>>(qkv);

    // 4. scores = (1/16) Q K^T (HMMA bf16x3): M=4096, N=4096, K=256
    hmma_gemm<CCH, CCH, HW><<<dim3(HW / 128, HW / 128, BATCH), 256, HMMA_SMEM>>>(
        qh, ql, kh, kl, scores, 0.0625f, CCH / 32, sNC, sNC, sSC);

    // 5. softmax + bf16 split of P
    softmax_split<<<BATCH * HW, 256>>>();

    // 6. attnout[q][c] = P @ V^T (HMMA bf16x3): M=4096, N=256, K=4096
    hmma_gemm<HW, HW, CCH><<<dim3(CCH / 128, HW / 128, BATCH), 256, HMMA_SMEM>>>(
        phh, pll, vh, vl, attnout, 1.f, HW / 32, sSC, sXN, sNC);

    // 7. out = x + W_proj @ attnout^T + b  (FFMA): M=256, N=4096, K=256
    gemm_kernel<0, 1, true, true><<<dim3(HW / BN, CCH / BM, BATCH), 256>>>(
        projw, attnout, out, projb, x, CCH, HW, CCH, 1.f, 0, sNC, sXN, sXN);
}

// round 4
// speedup vs baseline: 2.1782x; 1.2322x over previous
#include <cuda_runtime.h>
#include <cuda_bf16.h>
#include <cstdint>

#define BATCH 4
#define CCH 256
#define HW 4096
#define NQKV 768
#define NGROUPS 16
#define EPS 1e-5f

typedef __nv_bfloat16 bf16;

// ---------------- scratch (__device__ globals; allocation-free) ----------------
__device__ float g_scores[(size_t)BATCH * HW * HW];       // 256 MB
__device__ float g_mean[BATCH * NGROUPS];
__device__ float g_rstd[BATCH * NGROUPS];
__device__ bf16 g_xnt_h[(size_t)BATCH * HW * CCH];        // xn^T [b][n][c]
__device__ bf16 g_xnt_l[(size_t)BATCH * HW * CCH];
__device__ bf16 g_qkvt_h[(size_t)BATCH * HW * NQKV];      // [b][n][q|k|v]
__device__ bf16 g_qkvt_l[(size_t)BATCH * HW * NQKV];
__device__ bf16 g_wq_h[NQKV * CCH];                       // qkv_w split
__device__ bf16 g_wq_l[NQKV * CCH];
__device__ bf16 g_wp_h[CCH * CCH];                        // proj_w split
__device__ bf16 g_wp_l[CCH * CCH];
__device__ bf16 g_ph[(size_t)BATCH * HW * HW];            // P high, 128 MB
__device__ bf16 g_pl[(size_t)BATCH * HW * HW];            // P low,  128 MB
__device__ bf16 g_at_h[(size_t)BATCH * HW * CCH];         // attnout [b][q][c]
__device__ bf16 g_at_l[(size_t)BATCH * HW * CCH];

// ---------------- helpers ----------------
__device__ __forceinline__ uint32_t smem_u32(const void* p) {
    uint32_t a;
    asm("{ .reg .u64 t; cvta.to.shared.u64 t, %1; cvt.u32.u64 %0, t; }" : "=r"(a) : "l"(p));
    return a;
}
__device__ __forceinline__ void cp16(uint32_t s, const void* g) {
    asm volatile("cp.async.cg.shared.global [%0], [%1], 16;" :: "r"(s), "l"(g) : "memory");
}
__device__ __forceinline__ void ldsm4(uint32_t& r0, uint32_t& r1, uint32_t& r2, uint32_t& r3,
                                      uint32_t a) {
    asm volatile("ldmatrix.sync.aligned.m8n8.x4.shared.b16 {%0,%1,%2,%3}, [%4];"
                 : "=r"(r0), "=r"(r1), "=r"(r2), "=r"(r3) : "r"(a));
}
__device__ __forceinline__ void ldsm4t(uint32_t& r0, uint32_t& r1, uint32_t& r2, uint32_t& r3,
                                       uint32_t a) {
    asm volatile("ldmatrix.sync.aligned.m8n8.x4.trans.shared.b16 {%0,%1,%2,%3}, [%4];"
                 : "=r"(r0), "=r"(r1), "=r"(r2), "=r"(r3) : "r"(a));
}
__device__ __forceinline__ void mma_bf16(float* c, const uint32_t* a, const uint32_t* b) {
    asm volatile(
        "mma.sync.aligned.m16n8k16.row.col.f32.bf16.bf16.f32 "
        "{%0,%1,%2,%3}, {%4,%5,%6,%7}, {%8,%9}, {%0,%1,%2,%3};"
        : "+f"(c[0]), "+f"(c[1]), "+f"(c[2]), "+f"(c[3])
        : "r"(a[0]), "r"(a[1]), "r"(a[2]), "r"(a[3]), "r"(b[0]), "r"(b[1]));
}
__device__ __forceinline__ void split2(float v, bf16& h, bf16& l) {
    h = __float2bfloat16_rn(v);
    l = __float2bfloat16_rn(v - __bfloat162float(h));
}

// ---------------- GroupNorm ----------------
__global__ void gn_stats(const float* __restrict__ x) {
    int bg = blockIdx.x;
    const float4* p = (const float4*)(x + (size_t)bg * 16 * HW);
    float s = 0.f, sq = 0.f;
    for (int i = threadIdx.x; i < 16384; i += 256) {
        float4 v = p[i];
        s  += v.x + v.y + v.z + v.w;
        sq += v.x*v.x + v.y*v.y + v.z*v.z + v.w*v.w;
    }
    __shared__ float ss[256], sz[256];
    ss[threadIdx.x] = s; sz[threadIdx.x] = sq;
    __syncthreads();
    for (int o = 128; o > 0; o >>= 1) {
        if (threadIdx.x < o) { ss[threadIdx.x] += ss[threadIdx.x + o]; sz[threadIdx.x] += sz[threadIdx.x + o]; }
        __syncthreads();
    }
    if (threadIdx.x == 0) {
        float m = ss[0] * (1.f / 65536.f);
        float v = sz[0] * (1.f / 65536.f) - m * m;
        g_mean[bg] = m;
        g_rstd[bg] = rsqrtf(v + EPS);
    }
}

// GroupNorm apply + transpose + bf16 split: x[b][c][n] -> xnt_h/l [b][n][c]
__global__ void gn_apply_t(const float* __restrict__ x, const float* __restrict__ w,
                           const float* __restrict__ bgn) {
    __shared__ float t[32][33];
    int b = blockIdx.z;
    int n0 = blockIdx.x * 32, c0 = blockIdx.y * 32;
    int tx = threadIdx.x, ty = threadIdx.y;
    const float* src = x + (size_t)b * CCH * HW;
    #pragma unroll
    for (int j = 0; j < 4; j++) {
        int c = c0 + ty + j * 8;
        int bg = b * NGROUPS + (c >> 4);
        float sc = g_rstd[bg] * w[c];
        float sh = bgn[c] - g_mean[bg] * sc;
        t[ty + j * 8][tx] = src[(size_t)c * HW + n0 + tx] * sc + sh;
    }
    __syncthreads();
    bf16* dh = g_xnt_h + (size_t)b * HW * CCH;
    bf16* dl = g_xnt_l + (size_t)b * HW * CCH;
    #pragma unroll
    for (int j = 0; j < 4; j++) {
        float v = t[tx][ty + j * 8];
        bf16 h, l; split2(v, h, l);
        size_t o = (size_t)(n0 + ty + j * 8) * CCH + c0 + tx;
        dh[o] = h; dl[o] = l;
    }
}

// ---------------- weight split ----------------
__global__ void w_split(const float* __restrict__ w, bf16* __restrict__ h,
                        bf16* __restrict__ l, int n) {
    int i = blockIdx.x * 256 + threadIdx.x;
    if (i < n) {
        bf16 hh, ll; split2(w[i], hh, ll);
        h[i] = hh; l[i] = ll;
    }
}

// ---------------- softmax: fp32 scores -> bf16 h/l probabilities ----------------
__global__ void softmax_split() {
    size_t row = blockIdx.x;
    const float4* p4 = (const float4*)(g_scores + row * (size_t)HW);
    float4 v[4];
    float mx = -1e30f;
    #pragma unroll
    for (int j = 0; j < 4; j++) {
        v[j] = p4[threadIdx.x + j * 256];
        mx = fmaxf(mx, fmaxf(fmaxf(v[j].x, v[j].y), fmaxf(v[j].z, v[j].w)));
    }
    __shared__ float sm[256];
    sm[threadIdx.x] = mx;
    __syncthreads();
    for (int o = 128; o > 0; o >>= 1) {
        if (threadIdx.x < o) sm[threadIdx.x] = fmaxf(sm[threadIdx.x], sm[threadIdx.x + o]);
        __syncthreads();
    }
    mx = sm[0];
    __syncthreads();
    float s = 0.f;
    #pragma unroll
    for (int j = 0; j < 4; j++) {
        v[j].x = __expf(v[j].x - mx); v[j].y = __expf(v[j].y - mx);
        v[j].z = __expf(v[j].z - mx); v[j].w = __expf(v[j].w - mx);
        s += v[j].x + v[j].y + v[j].z + v[j].w;
    }
    sm[threadIdx.x] = s;
    __syncthreads();
    for (int o = 128; o > 0; o >>= 1) {
        if (threadIdx.x < o) sm[threadIdx.x] += sm[threadIdx.x + o];
        __syncthreads();
    }
    float inv = 1.f / sm[0];
    bf16* oh = g_ph + row * (size_t)HW;
    bf16* ol = g_pl + row * (size_t)HW;
    #pragma unroll
    for (int j = 0; j < 4; j++) {
        float f[4] = {v[j].x * inv, v[j].y * inv, v[j].z * inv, v[j].w * inv};
        bf16 hh[4], ll[4];
        #pragma unroll
        for (int i = 0; i < 4; i++) split2(f[i], hh[i], ll[i]);
        size_t o = (size_t)(threadIdx.x + j * 256) * 4;
        *(__nv_bfloat162*)(oh + o)     = __nv_bfloat162(hh[0], hh[1]);
        *(__nv_bfloat162*)(oh + o + 2) = __nv_bfloat162(hh[2], hh[3]);
        *(__nv_bfloat162*)(ol + o)     = __nv_bfloat162(ll[0], ll[1]);
        *(__nv_bfloat162*)(ol + o + 2) = __nv_bfloat162(ll[2], ll[3]);
    }
}

// ---------------- HMMA bf16x3 GEMM, 128x128 tile, non-trans B ----------------
// A: [m][K] bf16 (stride ASTR), B: [n][K] bf16 (stride BSTR), both h+l.
// EPI 0: outf = alpha * acc (scores)
// EPI 1: outh/outl = split(acc + bias[col])   (qkv)
// EPI 2: outf = acc + bias[row] + resid       (proj)
#define TILE_B 10240
#define STAGE_B 40960
#define HMMA_SMEM (2 * STAGE_B)

template<int ASTR, int BSTR, int OSTR, int EPI>
__global__ __launch_bounds__(256, 1)
void hmma128(const bf16* __restrict__ Ah_, const bf16* __restrict__ Al_,
             const bf16* __restrict__ Bh_, const bf16* __restrict__ Bl_,
             float* __restrict__ outf, bf16* __restrict__ outh, bf16* __restrict__ outl,
             const float* __restrict__ bias, const float* __restrict__ resid,
             float alpha, int ksteps, size_t aB, size_t bB, size_t oB, size_t rB) {
    extern __shared__ char smem[];
    const uint32_t sb = smem_u32(smem);
    const int tid = threadIdx.x;
    const int wid = tid >> 5, lane = tid & 31;
    const int b = blockIdx.z;
    const int bm = blockIdx.y * 128;
    const int bn = blockIdx.x * 128;
    const int wm = wid & 1, wn = wid >> 1;

    const bf16* Ah = Ah_ + (size_t)b * aB + (size_t)bm * ASTR;
    const bf16* Al = Al_ + (size_t)b * aB + (size_t)bm * ASTR;
    const bf16* Bh = Bh_ + (size_t)b * bB + (size_t)bn * BSTR;
    const bf16* Bl = Bl_ + (size_t)b * bB + (size_t)bn * BSTR;

    const int u0row = tid >> 2, u0c = tid & 3;
    const int u1row = (tid + 256) >> 2, u1c = (tid + 256) & 3;

    float acc[4][4][4];
    #pragma unroll
    for (int mi = 0; mi < 4; mi++)
        #pragma unroll
        for (int ni = 0; ni < 4; ni++)
            #pragma unroll
            for (int r = 0; r < 4; r++) acc[mi][ni][r] = 0.f;

    const int g = lane >> 3;
    const int lrow = (g & 1) * 8 + (lane & 7);
    const int lkb  = (g >> 1) * 16;

    auto load_stage = [&](int ks, int buf) {
        const uint32_t base = sb + buf * STAGE_B;
        const int k0 = ks * 32;
        uint32_t so0 = base + u0row * 80 + u0c * 16;
        uint32_t so1 = base + u1row * 80 + u1c * 16;
        size_t ga0 = (size_t)u0row * ASTR + k0 + u0c * 8;
        size_t ga1 = (size_t)u1row * ASTR + k0 + u1c * 8;
        size_t gb0 = (size_t)u0row * BSTR + k0 + u0c * 8;
        size_t gb1 = (size_t)u1row * BSTR + k0 + u1c * 8;
        cp16(so0,              Ah + ga0);
        cp16(so1,              Ah + ga1);
        cp16(so0 + TILE_B,     Al + ga0);
        cp16(so1 + TILE_B,     Al + ga1);
        cp16(so0 + 2 * TILE_B, Bh + gb0);
        cp16(so1 + 2 * TILE_B, Bh + gb1);
        cp16(so0 + 3 * TILE_B, Bl + gb0);
        cp16(so1 + 3 * TILE_B, Bl + gb1);
    };

    load_stage(0, 0);
    asm volatile("cp.async.commit_group;" ::: "memory");

    for (int ks = 0; ks < ksteps; ks++) {
        const int buf = ks & 1;
        if (ks + 1 < ksteps) {
            load_stage(ks + 1, buf ^ 1);
            asm volatile("cp.async.commit_group;" ::: "memory");
            asm volatile("cp.async.wait_group 1;" ::: "memory");
        } else {
            asm volatile("cp.async.wait_group 0;" ::: "memory");
        }
        __syncthreads();

        const uint32_t base = sb + buf * STAGE_B;
        #pragma unroll
        for (int k16 = 0; k16 < 2; k16++) {
            uint32_t ah[4][4], al[4][4], bh[4][2], bl[4][2];
            #pragma unroll
            for (int mi = 0; mi < 4; mi++) {
                uint32_t ra = base + (wm * 64 + mi * 16 + lrow) * 80 + k16 * 32 + lkb;
                ldsm4(ah[mi][0], ah[mi][1], ah[mi][2], ah[mi][3], ra);
                ldsm4(al[mi][0], al[mi][1], al[mi][2], al[mi][3], ra + TILE_B);
            }
            #pragma unroll
            for (int p = 0; p < 2; p++) {
                uint32_t rb = base + 2 * TILE_B + (wn * 32 + p * 16 + lrow) * 80 + k16 * 32 + lkb;
                uint32_t r0, r1, r2, r3;
                ldsm4(r0, r1, r2, r3, rb);
                bh[2*p][0] = r0; bh[2*p+1][0] = r1; bh[2*p][1] = r2; bh[2*p+1][1] = r3;
                ldsm4(r0, r1, r2, r3, rb + TILE_B);
                bl[2*p][0] = r0; bl[2*p+1][0] = r1; bl[2*p][1] = r2; bl[2*p+1][1] = r3;
            }
            #pragma unroll
            for (int mi = 0; mi < 4; mi++)
                #pragma unroll
                for (int ni = 0; ni < 4; ni++) {
                    mma_bf16(acc[mi][ni], ah[mi], bh[ni]);
                    mma_bf16(acc[mi][ni], ah[mi], bl[ni]);
                    mma_bf16(acc[mi][ni], al[mi], bh[ni]);
                }
        }
        __syncthreads();
    }

    // epilogue
    #pragma unroll
    for (int mi = 0; mi < 4; mi++) {
        int r0 = bm + wm * 64 + mi * 16 + (lane >> 2);
        #pragma unroll
        for (int ni = 0; ni < 4; ni++) {
            int col = bn + wn * 32 + ni * 8 + (lane & 3) * 2;
            #pragma unroll
            for (int half = 0; half < 2; half++) {
                int row = r0 + half * 8;
                float v0 = acc[mi][ni][half * 2 + 0];
                float v1 = acc[mi][ni][half * 2 + 1];
                if (EPI == 0) {
                    float* o = outf + (size_t)b * oB + (size_t)row * OSTR + col;
                    *(float2*)o = make_float2(v0 * alpha, v1 * alpha);
                } else if (EPI == 1) {
                    v0 += bias[col]; v1 += bias[col + 1];
                    bf16 h0, l0, h1, l1;
                    split2(v0, h0, l0); split2(v1, h1, l1);
                    size_t o = (size_t)b * oB + (size_t)row * OSTR + col;
                    *(__nv_bfloat162*)(outh + o) = __nv_bfloat162(h0, h1);
                    *(__nv_bfloat162*)(outl + o) = __nv_bfloat162(l0, l1);
                } else {
                    size_t o = (size_t)b * oB + (size_t)row * OSTR + col;
                    const float* rp = resid + (size_t)b * rB + (size_t)row * OSTR + col;
                    float bv = bias[row];
                    float2 r = *(const float2*)rp;
                    *(float2*)(outf + o) = make_float2(v0 + bv + r.x, v1 + bv + r.y);
                }
            }
        }
    }
}

// ---------------- HMMA bf16x3 PV GEMM: 128x256 tile, trans-B ----------------
// A = P [q][k] h/l (stride HW). B = V stored [k][c] rows inside qkvT (+512 col offset).
// out: attn h/l [q][c] stride CCH.
#define PV_A_B 10240
#define PV_BROW 528
#define PV_B_B (32 * PV_BROW)      // 16896
#define PV_STAGE (2 * PV_A_B + 2 * PV_B_B)   // 54272
#define PV_SMEM (2 * PV_STAGE)

__global__ __launch_bounds__(256, 1)
void hmma_pv(const bf16* __restrict__ Ph, const bf16* __restrict__ Pl,
             const bf16* __restrict__ qkvh, const bf16* __restrict__ qkvl) {
    extern __shared__ char smem[];
    const uint32_t sb = smem_u32(smem);
    const int tid = threadIdx.x;
    const int wid = tid >> 5, lane = tid & 31;
    const int b = blockIdx.z;
    const int bm = blockIdx.y * 128;
    const int wm = wid & 1, wn = wid >> 1;   // warp: 64 m rows, 64 n cols

    const bf16* Ah = Ph + (size_t)b * HW * HW + (size_t)bm * HW;
    const bf16* Al = Pl + (size_t)b * HW * HW + (size_t)bm * HW;
    const bf16* Bh = qkvh + (size_t)b * HW * NQKV + 512;   // V columns
    const bf16* Bl = qkvl + (size_t)b * HW * NQKV + 512;

    float acc[4][8][4];
    #pragma unroll
    for (int mi = 0; mi < 4; mi++)
        #pragma unroll
        for (int ni = 0; ni < 8; ni++)
            #pragma unroll
            for (int r = 0; r < 4; r++) acc[mi][ni][r] = 0.f;

    const int g = lane >> 3;
    const int lrow = (g & 1) * 8 + (lane & 7);
    const int lkb  = (g >> 1) * 16;

    auto load_stage = [&](int ks, int buf) {
        const uint32_t base = sb + buf * PV_STAGE;
        const int k0 = ks * 32;
        // A: 128 rows x 64B (4 chunks), h+l
        #pragma unroll
        for (int u = tid; u < 512; u += 256) {
            int row = u >> 2, c = u & 3;
            uint32_t so = base + row * 80 + c * 16;
            size_t ga = (size_t)row * HW + k0 + c * 8;
            cp16(so,          Ah + ga);
            cp16(so + PV_A_B, Al + ga);
        }
        // B: 32 k-rows x 512B (32 chunks), h+l
        #pragma unroll
        for (int u = tid; u < 1024; u += 256) {
            int row = u >> 5, c = u & 31;
            uint32_t so = base + 2 * PV_A_B + row * PV_BROW + c * 16;
            size_t gb = (size_t)(k0 + row) * NQKV + c * 8;
            cp16(so,          Bh + gb);
            cp16(so + PV_B_B, Bl + gb);
        }
    };

    load_stage(0, 0);
    asm volatile("cp.async.commit_group;" ::: "memory");

    const int ksteps = HW / 32;
    for (int ks = 0; ks < ksteps; ks++) {
        const int buf = ks & 1;
        if (ks + 1 < ksteps) {
            load_stage(ks + 1, buf ^ 1);
            asm volatile("cp.async.commit_group;" ::: "memory");
            asm volatile("cp.async.wait_group 1;" ::: "memory");
        } else {
            asm volatile("cp.async.wait_group 0;" ::: "memory");
        }
        __syncthreads();

        const uint32_t base = sb + buf * PV_STAGE;
        #pragma unroll
        for (int k16 = 0; k16 < 2; k16++) {
            uint32_t ah[4][4], al[4][4], bh[8][2], bl[8][2];
            #pragma unroll
            for (int mi = 0; mi < 4; mi++) {
                uint32_t ra = base + (wm * 64 + mi * 16 + lrow) * 80 + k16 * 32 + lkb;
                ldsm4(ah[mi][0], ah[mi][1], ah[mi][2], ah[mi][3], ra);
                ldsm4(al[mi][0], al[mi][1], al[mi][2], al[mi][3], ra + PV_A_B);
            }
            // B via trans ldmatrix: tiles (k0-7,n0-7),(k8-15,n0-7),(k0-7,n8-15),(k8-15,n8-15)
            #pragma unroll
            for (int p = 0; p < 4; p++) {
                int krl = k16 * 16 + (g & 1) * 8 + (lane & 7);
                int ncl = wn * 64 + p * 16 + (g >> 1) * 8;
                uint32_t rb = base + 2 * PV_A_B + krl * PV_BROW + ncl * 2;
                uint32_t r0, r1, r2, r3;
                ldsm4t(r0, r1, r2, r3, rb);
                bh[2*p][0] = r0; bh[2*p][1] = r1; bh[2*p+1][0] = r2; bh[2*p+1][1] = r3;
                ldsm4t(r0, r1, r2, r3, rb + PV_B_B);
                bl[2*p][0] = r0; bl[2*p][1] = r1; bl[2*p+1][0] = r2; bl[2*p+1][1] = r3;
            }
            #pragma unroll
            for (int mi = 0; mi < 4; mi++)
                #pragma unroll
                for (int ni = 0; ni < 8; ni++) {
                    mma_bf16(acc[mi][ni], ah[mi], bh[ni]);
                    mma_bf16(acc[mi][ni], ah[mi], bl[ni]);
                    mma_bf16(acc[mi][ni], al[mi], bh[ni]);
                }
        }
        __syncthreads();
    }

    // epilogue: split to attn h/l [q][c]
    bf16* oh = g_at_h + (size_t)b * HW * CCH;
    bf16* ol = g_at_l + (size_t)b * HW * CCH;
    #pragma unroll
    for (int mi = 0; mi < 4; mi++) {
        int r0 = bm + wm * 64 + mi * 16 + (lane >> 2);
        #pragma unroll
        for (int ni = 0; ni < 8; ni++) {
            int col = wn * 64 + ni * 8 + (lane & 3) * 2;
            #pragma unroll
            for (int half = 0; half < 2; half++) {
                int row = r0 + half * 8;
                float v0 = acc[mi][ni][half * 2 + 0];
                float v1 = acc[mi][ni][half * 2 + 1];
                bf16 h0, l0, h1, l1;
                split2(v0, h0, l0); split2(v1, h1, l1);
                size_t o = (size_t)row * CCH + col;
                *(__nv_bfloat162*)(oh + o) = __nv_bfloat162(h0, h1);
                *(__nv_bfloat162*)(ol + o) = __nv_bfloat162(l0, l1);
            }
        }
    }
}

// ---------------- launch ----------------
extern "C" void kernel_launch(void* const* d_in, const int* in_sizes, int n_in,
                              void* d_out, int out_size) {
    const float* x     = (const float*)d_in[0];
    const float* gnw   = (const float*)d_in[1];
    const float* gnb   = (const float*)d_in[2];
    const float* qkvw  = (const float*)d_in[3];
    const float* qkvb  = (const float*)d_in[4];
    const float* projw = (const float*)d_in[5];
    const float* projb = (const float*)d_in[6];
    float* out = (float*)d_out;

    float* scores;
    bf16 *xnh, *xnl, *qth, *qtl, *wqh, *wql, *wph, *wpl, *phh, *pll, *ath, *atl;
    cudaGetSymbolAddress((void**)&scores, g_scores);
    cudaGetSymbolAddress((void**)&xnh, g_xnt_h);
    cudaGetSymbolAddress((void**)&xnl, g_xnt_l);
    cudaGetSymbolAddress((void**)&qth, g_qkvt_h);
    cudaGetSymbolAddress((void**)&qtl, g_qkvt_l);
    cudaGetSymbolAddress((void**)&wqh, g_wq_h);
    cudaGetSymbolAddress((void**)&wql, g_wq_l);
    cudaGetSymbolAddress((void**)&wph, g_wp_h);
    cudaGetSymbolAddress((void**)&wpl, g_wp_l);
    cudaGetSymbolAddress((void**)&phh, g_ph);
    cudaGetSymbolAddress((void**)&pll, g_pl);
    cudaGetSymbolAddress((void**)&ath, g_at_h);
    cudaGetSymbolAddress((void**)&atl, g_at_l);

    const size_t sNC  = (size_t)HW * CCH;      // 1M
    const size_t sQT  = (size_t)HW * NQKV;     // 3M
    const size_t sSC  = (size_t)HW * HW;       // 16M
    const size_t sXN  = (size_t)CCH * HW;

    cudaFuncSetAttribute((const void*)hmma128<CCH, CCH, NQKV, 1>,
                         cudaFuncAttributeMaxDynamicSharedMemorySize, HMMA_SMEM);
    cudaFuncSetAttribute((const void*)hmma128<NQKV, NQKV, HW, 0>,
                         cudaFuncAttributeMaxDynamicSharedMemorySize, HMMA_SMEM);
    cudaFuncSetAttribute((const void*)hmma128<CCH, CCH, HW, 2>,
                         cudaFuncAttributeMaxDynamicSharedMemorySize, HMMA_SMEM);
    cudaFuncSetAttribute((const void*)hmma_pv,
                         cudaFuncAttributeMaxDynamicSharedMemorySize, PV_SMEM);

    // 1. GroupNorm (+ transpose + split)
    gn_stats<<<BATCH * NGROUPS, 256>>>(x);
    gn_apply_t<<<dim3(HW / 32, CCH / 32, BATCH), dim3(32, 8)>>>(x, gnw, gnb);

    // 2. weight splits
    w_split<<<(NQKV * CCH + 255) / 256, 256>>>(qkvw, wqh, wql, NQKV * CCH);
    w_split<<<(CCH * CCH + 255) / 256, 256>>>(projw, wph, wpl, CCH * CCH);

    // 3. qkvT[n][o] = xnT[n][:] . W[o][:] + b[o] : M=4096, N=768, K=256
    hmma128<CCH, CCH, NQKV, 1><<<dim3(NQKV / 128, HW / 128, BATCH), 256, HMMA_SMEM>>>(
        xnh, xnl, wqh, wql, nullptr, qth, qtl, qkvb, nullptr, 1.f, CCH / 32,
        sNC, 0, sQT, 0);

    // 4. scores = (1/16) Q K^T : M=N=4096, K=256 ; A=qkvT[:, 0:256], B=qkvT[:, 256:512]
    hmma128<NQKV, NQKV, HW, 0><<<dim3(HW / 128, HW / 128, BATCH), 256, HMMA_SMEM>>>(
        qth, qtl, qth + 256, qtl + 256, scores, nullptr, nullptr, nullptr, nullptr,
        0.0625f, CCH / 32, sQT, sQT, sSC, 0);

    // 5. softmax + split
    softmax_split<<<BATCH * HW, 256>>>();

    // 6. attn[q][c] = P . V : M=4096, N=256(full), K=4096 ; trans-B from qkvT[:, 512:768]
    hmma_pv<<<dim3(1, HW / 128, BATCH), 256, PV_SMEM>>>(phh, pll, qth, qtl);

    // 7. out[co][n] = projw[co][:] . attn[n][:] + b[co] + x : M=256, N=4096, K=256
    hmma128<CCH, CCH, HW, 2><<<dim3(HW / 128, CCH / 128, BATCH), 256, HMMA_SMEM>>>(
        wph, wpl, ath, atl, out, nullptr, nullptr, projb, x, 1.f, CCH / 32,
        0, sNC, sXN, sXN);
}

// round 5
// speedup vs baseline: 4.1240x; 1.8933x over previous
#include <cuda_runtime.h>
#include <cuda_bf16.h>
#include <cuda_fp16.h>
#include <cstdint>

#define BATCH 4
#define CCH 256
#define HW 4096
#define NQKV 768
#define NGROUPS 16
#define EPS 1e-5f

typedef __nv_bfloat16 bf16;

// ---------------- scratch ----------------
__device__ float g_scores[(size_t)BATCH * HW * HW];       // 256 MB fp32
__device__ __half g_p16[(size_t)BATCH * HW * HW];         // 128 MB fp16 P
__device__ __half g_qkvt[(size_t)BATCH * HW * NQKV];      // 24 MB fp16 [n][q|k|v]
__device__ float g_mean[BATCH * NGROUPS];
__device__ float g_rstd[BATCH * NGROUPS];
__device__ bf16 g_xnt_h[(size_t)BATCH * HW * CCH];
__device__ bf16 g_xnt_l[(size_t)BATCH * HW * CCH];
__device__ bf16 g_wq_h[NQKV * CCH];
__device__ bf16 g_wq_l[NQKV * CCH];
__device__ bf16 g_wp_h[CCH * CCH];
__device__ bf16 g_wp_l[CCH * CCH];
__device__ bf16 g_at_h[(size_t)BATCH * HW * CCH];
__device__ bf16 g_at_l[(size_t)BATCH * HW * CCH];

// ---------------- helpers ----------------
__device__ __forceinline__ uint32_t smem_u32(const void* p) {
    uint32_t a;
    asm("{ .reg .u64 t; cvta.to.shared.u64 t, %1; cvt.u32.u64 %0, t; }" : "=r"(a) : "l"(p));
    return a;
}
__device__ __forceinline__ void cp16(uint32_t s, const void* g) {
    asm volatile("cp.async.cg.shared.global [%0], [%1], 16;" :: "r"(s), "l"(g) : "memory");
}
__device__ __forceinline__ void ldsm4(uint32_t& r0, uint32_t& r1, uint32_t& r2, uint32_t& r3,
                                      uint32_t a) {
    asm volatile("ldmatrix.sync.aligned.m8n8.x4.shared.b16 {%0,%1,%2,%3}, [%4];"
                 : "=r"(r0), "=r"(r1), "=r"(r2), "=r"(r3) : "r"(a));
}
__device__ __forceinline__ void ldsm4t(uint32_t& r0, uint32_t& r1, uint32_t& r2, uint32_t& r3,
                                       uint32_t a) {
    asm volatile("ldmatrix.sync.aligned.m8n8.x4.trans.shared.b16 {%0,%1,%2,%3}, [%4];"
                 : "=r"(r0), "=r"(r1), "=r"(r2), "=r"(r3) : "r"(a));
}
__device__ __forceinline__ void mma_bf16(float* c, const uint32_t* a, const uint32_t* b) {
    asm volatile(
        "mma.sync.aligned.m16n8k16.row.col.f32.bf16.bf16.f32 "
        "{%0,%1,%2,%3}, {%4,%5,%6,%7}, {%8,%9}, {%0,%1,%2,%3};"
        : "+f"(c[0]), "+f"(c[1]), "+f"(c[2]), "+f"(c[3])
        : "r"(a[0]), "r"(a[1]), "r"(a[2]), "r"(a[3]), "r"(b[0]), "r"(b[1]));
}
__device__ __forceinline__ void mma_f16(float* c, const uint32_t* a, const uint32_t* b) {
    asm volatile(
        "mma.sync.aligned.m16n8k16.row.col.f32.f16.f16.f32 "
        "{%0,%1,%2,%3}, {%4,%5,%6,%7}, {%8,%9}, {%0,%1,%2,%3};"
        : "+f"(c[0]), "+f"(c[1]), "+f"(c[2]), "+f"(c[3])
        : "r"(a[0]), "r"(a[1]), "r"(a[2]), "r"(a[3]), "r"(b[0]), "r"(b[1]));
}
__device__ __forceinline__ void split2(float v, bf16& h, bf16& l) {
    h = __float2bfloat16_rn(v);
    l = __float2bfloat16_rn(v - __bfloat162float(h));
}

// ---------------- GroupNorm ----------------
__global__ void gn_stats(const float* __restrict__ x) {
    int bg = blockIdx.x;
    const float4* p = (const float4*)(x + (size_t)bg * 16 * HW);
    float s = 0.f, sq = 0.f;
    for (int i = threadIdx.x; i < 16384; i += 256) {
        float4 v = p[i];
        s  += v.x + v.y + v.z + v.w;
        sq += v.x*v.x + v.y*v.y + v.z*v.z + v.w*v.w;
    }
    __shared__ float ss[256], sz[256];
    ss[threadIdx.x] = s; sz[threadIdx.x] = sq;
    __syncthreads();
    for (int o = 128; o > 0; o >>= 1) {
        if (threadIdx.x < o) { ss[threadIdx.x] += ss[threadIdx.x + o]; sz[threadIdx.x] += sz[threadIdx.x + o]; }
        __syncthreads();
    }
    if (threadIdx.x == 0) {
        float m = ss[0] * (1.f / 65536.f);
        float v = sz[0] * (1.f / 65536.f) - m * m;
        g_mean[bg] = m;
        g_rstd[bg] = rsqrtf(v + EPS);
    }
}

__global__ void gn_apply_t(const float* __restrict__ x, const float* __restrict__ w,
                           const float* __restrict__ bgn) {
    __shared__ float t[32][33];
    int b = blockIdx.z;
    int n0 = blockIdx.x * 32, c0 = blockIdx.y * 32;
    int tx = threadIdx.x, ty = threadIdx.y;
    const float* src = x + (size_t)b * CCH * HW;
    #pragma unroll
    for (int j = 0; j < 4; j++) {
        int c = c0 + ty + j * 8;
        int bg = b * NGROUPS + (c >> 4);
        float sc = g_rstd[bg] * w[c];
        float sh = bgn[c] - g_mean[bg] * sc;
        t[ty + j * 8][tx] = src[(size_t)c * HW + n0 + tx] * sc + sh;
    }
    __syncthreads();
    bf16* dh = g_xnt_h + (size_t)b * HW * CCH;
    bf16* dl = g_xnt_l + (size_t)b * HW * CCH;
    #pragma unroll
    for (int j = 0; j < 4; j++) {
        float v = t[tx][ty + j * 8];
        bf16 h, l; split2(v, h, l);
        size_t o = (size_t)(n0 + ty + j * 8) * CCH + c0 + tx;
        dh[o] = h; dl[o] = l;
    }
}

__global__ void w_split(const float* __restrict__ w, bf16* __restrict__ h,
                        bf16* __restrict__ l, int n) {
    int i = blockIdx.x * 256 + threadIdx.x;
    if (i < n) {
        bf16 hh, ll; split2(w[i], hh, ll);
        h[i] = hh; l[i] = ll;
    }
}

// ---------------- softmax: fp32 scores -> fp16 probabilities ----------------
__global__ void softmax_p16() {
    size_t row = blockIdx.x;
    const float4* p4 = (const float4*)(g_scores + row * (size_t)HW);
    float4 v[4];
    float mx = -1e30f;
    #pragma unroll
    for (int j = 0; j < 4; j++) {
        v[j] = p4[threadIdx.x + j * 256];
        mx = fmaxf(mx, fmaxf(fmaxf(v[j].x, v[j].y), fmaxf(v[j].z, v[j].w)));
    }
    __shared__ float sm[256];
    sm[threadIdx.x] = mx;
    __syncthreads();
    for (int o = 128; o > 0; o >>= 1) {
        if (threadIdx.x < o) sm[threadIdx.x] = fmaxf(sm[threadIdx.x], sm[threadIdx.x + o]);
        __syncthreads();
    }
    mx = sm[0];
    __syncthreads();
    float s = 0.f;
    #pragma unroll
    for (int j = 0; j < 4; j++) {
        v[j].x = __expf(v[j].x - mx); v[j].y = __expf(v[j].y - mx);
        v[j].z = __expf(v[j].z - mx); v[j].w = __expf(v[j].w - mx);
        s += v[j].x + v[j].y + v[j].z + v[j].w;
    }
    sm[threadIdx.x] = s;
    __syncthreads();
    for (int o = 128; o > 0; o >>= 1) {
        if (threadIdx.x < o) sm[threadIdx.x] += sm[threadIdx.x + o];
        __syncthreads();
    }
    float inv = 1.f / sm[0];
    __half* op = g_p16 + row * (size_t)HW;
    #pragma unroll
    for (int j = 0; j < 4; j++) {
        __half2 h0 = __floats2half2_rn(v[j].x * inv, v[j].y * inv);
        __half2 h1 = __floats2half2_rn(v[j].z * inv, v[j].w * inv);
        size_t o = (size_t)(threadIdx.x + j * 256) * 4;
        *(__half2*)(op + o)     = h0;
        *(__half2*)(op + o + 2) = h1;
    }
}

// ---------------- HMMA bf16x3 GEMM, 128x128 tile (qkv EPI1->fp16 out, proj EPI2) ----------------
#define TILE_B 10240
#define STAGE_B 40960
#define HMMA_SMEM (2 * STAGE_B)

template<int ASTR, int BSTR, int OSTR, int EPI>
__global__ __launch_bounds__(256, 1)
void hmma128(const bf16* __restrict__ Ah_, const bf16* __restrict__ Al_,
             const bf16* __restrict__ Bh_, const bf16* __restrict__ Bl_,
             float* __restrict__ outf, __half* __restrict__ outh,
             const float* __restrict__ bias, const float* __restrict__ resid,
             float alpha, int ksteps, size_t aB, size_t bB, size_t oB, size_t rB) {
    extern __shared__ char smem[];
    const uint32_t sb = smem_u32(smem);
    const int tid = threadIdx.x;
    const int wid = tid >> 5, lane = tid & 31;
    const int b = blockIdx.z;
    const int bm = blockIdx.y * 128;
    const int bn = blockIdx.x * 128;
    const int wm = wid & 1, wn = wid >> 1;

    const bf16* Ah = Ah_ + (size_t)b * aB + (size_t)bm * ASTR;
    const bf16* Al = Al_ + (size_t)b * aB + (size_t)bm * ASTR;
    const bf16* Bh = Bh_ + (size_t)b * bB + (size_t)bn * BSTR;
    const bf16* Bl = Bl_ + (size_t)b * bB + (size_t)bn * BSTR;

    const int u0row = tid >> 2, u0c = tid & 3;
    const int u1row = (tid + 256) >> 2, u1c = (tid + 256) & 3;

    float acc[4][4][4];
    #pragma unroll
    for (int mi = 0; mi < 4; mi++)
        #pragma unroll
        for (int ni = 0; ni < 4; ni++)
            #pragma unroll
            for (int r = 0; r < 4; r++) acc[mi][ni][r] = 0.f;

    const int g = lane >> 3;
    const int lrow = (g & 1) * 8 + (lane & 7);
    const int lkb  = (g >> 1) * 16;

    auto load_stage = [&](int ks, int buf) {
        const uint32_t base = sb + buf * STAGE_B;
        const int k0 = ks * 32;
        uint32_t so0 = base + u0row * 80 + u0c * 16;
        uint32_t so1 = base + u1row * 80 + u1c * 16;
        size_t ga0 = (size_t)u0row * ASTR + k0 + u0c * 8;
        size_t ga1 = (size_t)u1row * ASTR + k0 + u1c * 8;
        size_t gb0 = (size_t)u0row * BSTR + k0 + u0c * 8;
        size_t gb1 = (size_t)u1row * BSTR + k0 + u1c * 8;
        cp16(so0,              Ah + ga0);
        cp16(so1,              Ah + ga1);
        cp16(so0 + TILE_B,     Al + ga0);
        cp16(so1 + TILE_B,     Al + ga1);
        cp16(so0 + 2 * TILE_B, Bh + gb0);
        cp16(so1 + 2 * TILE_B, Bh + gb1);
        cp16(so0 + 3 * TILE_B, Bl + gb0);
        cp16(so1 + 3 * TILE_B, Bl + gb1);
    };

    load_stage(0, 0);
    asm volatile("cp.async.commit_group;" ::: "memory");

    for (int ks = 0; ks < ksteps; ks++) {
        const int buf = ks & 1;
        if (ks + 1 < ksteps) {
            load_stage(ks + 1, buf ^ 1);
            asm volatile("cp.async.commit_group;" ::: "memory");
            asm volatile("cp.async.wait_group 1;" ::: "memory");
        } else {
            asm volatile("cp.async.wait_group 0;" ::: "memory");
        }
        __syncthreads();

        const uint32_t base = sb + buf * STAGE_B;
        #pragma unroll
        for (int k16 = 0; k16 < 2; k16++) {
            uint32_t ah[4][4], al[4][4], bh[4][2], bl[4][2];
            #pragma unroll
            for (int mi = 0; mi < 4; mi++) {
                uint32_t ra = base + (wm * 64 + mi * 16 + lrow) * 80 + k16 * 32 + lkb;
                ldsm4(ah[mi][0], ah[mi][1], ah[mi][2], ah[mi][3], ra);
                ldsm4(al[mi][0], al[mi][1], al[mi][2], al[mi][3], ra + TILE_B);
            }
            #pragma unroll
            for (int p = 0; p < 2; p++) {
                uint32_t rb = base + 2 * TILE_B + (wn * 32 + p * 16 + lrow) * 80 + k16 * 32 + lkb;
                uint32_t r0, r1, r2, r3;
                ldsm4(r0, r1, r2, r3, rb);
                bh[2*p][0] = r0; bh[2*p+1][0] = r1; bh[2*p][1] = r2; bh[2*p+1][1] = r3;
                ldsm4(r0, r1, r2, r3, rb + TILE_B);
                bl[2*p][0] = r0; bl[2*p+1][0] = r1; bl[2*p][1] = r2; bl[2*p+1][1] = r3;
            }
            #pragma unroll
            for (int mi = 0; mi < 4; mi++)
                #pragma unroll
                for (int ni = 0; ni < 4; ni++) {
                    mma_bf16(acc[mi][ni], ah[mi], bh[ni]);
                    mma_bf16(acc[mi][ni], ah[mi], bl[ni]);
                    mma_bf16(acc[mi][ni], al[mi], bh[ni]);
                }
        }
        __syncthreads();
    }

    #pragma unroll
    for (int mi = 0; mi < 4; mi++) {
        int r0 = bm + wm * 64 + mi * 16 + (lane >> 2);
        #pragma unroll
        for (int ni = 0; ni < 4; ni++) {
            int col = bn + wn * 32 + ni * 8 + (lane & 3) * 2;
            #pragma unroll
            for (int half = 0; half < 2; half++) {
                int row = r0 + half * 8;
                float v0 = acc[mi][ni][half * 2 + 0];
                float v1 = acc[mi][ni][half * 2 + 1];
                if (EPI == 1) {
                    v0 += bias[col]; v1 += bias[col + 1];
                    size_t o = (size_t)b * oB + (size_t)row * OSTR + col;
                    *(__half2*)(outh + o) = __floats2half2_rn(v0, v1);
                } else {
                    size_t o = (size_t)b * oB + (size_t)row * OSTR + col;
                    const float* rp = resid + (size_t)b * rB + (size_t)row * OSTR + col;
                    float bv = bias[row];
                    float2 r = *(const float2*)rp;
                    *(float2*)(outf + o) = make_float2(v0 + bv + r.x, v1 + bv + r.y);
                }
            }
        }
    }
}

// ---------------- fp16 scores GEMM: 128x128 tile, K=256 ----------------
#define S_TILE 10240
#define S_STAGE 20480
#define S_SMEM (2 * S_STAGE)

__global__ __launch_bounds__(256, 2)
void hmma_s16(const __half* __restrict__ qkvt, float* __restrict__ outs) {
    extern __shared__ char smem[];
    const uint32_t sb = smem_u32(smem);
    const int tid = threadIdx.x;
    const int wid = tid >> 5, lane = tid & 31;
    const int b = blockIdx.z;
    const int bm = blockIdx.y * 128;
    const int bn = blockIdx.x * 128;
    const int wm = wid & 1, wn = wid >> 1;

    const __half* A = qkvt + (size_t)b * HW * NQKV + (size_t)bm * NQKV;         // q
    const __half* B = qkvt + (size_t)b * HW * NQKV + (size_t)bn * NQKV + 256;   // k

    const int u0row = tid >> 2, u0c = tid & 3;
    const int u1row = (tid + 256) >> 2, u1c = (tid + 256) & 3;

    float acc[4][4][4];
    #pragma unroll
    for (int mi = 0; mi < 4; mi++)
        #pragma unroll
        for (int ni = 0; ni < 4; ni++)
            #pragma unroll
            for (int r = 0; r < 4; r++) acc[mi][ni][r] = 0.f;

    const int g = lane >> 3;
    const int lrow = (g & 1) * 8 + (lane & 7);
    const int lkb  = (g >> 1) * 16;

    auto load_stage = [&](int ks, int buf) {
        const uint32_t base = sb + buf * S_STAGE;
        const int k0 = ks * 32;
        uint32_t so0 = base + u0row * 80 + u0c * 16;
        uint32_t so1 = base + u1row * 80 + u1c * 16;
        cp16(so0,          A + (size_t)u0row * NQKV + k0 + u0c * 8);
        cp16(so1,          A + (size_t)u1row * NQKV + k0 + u1c * 8);
        cp16(so0 + S_TILE, B + (size_t)u0row * NQKV + k0 + u0c * 8);
        cp16(so1 + S_TILE, B + (size_t)u1row * NQKV + k0 + u1c * 8);
    };

    load_stage(0, 0);
    asm volatile("cp.async.commit_group;" ::: "memory");

    const int ksteps = CCH / 32;
    for (int ks = 0; ks < ksteps; ks++) {
        const int buf = ks & 1;
        if (ks + 1 < ksteps) {
            load_stage(ks + 1, buf ^ 1);
            asm volatile("cp.async.commit_group;" ::: "memory");
            asm volatile("cp.async.wait_group 1;" ::: "memory");
        } else {
            asm volatile("cp.async.wait_group 0;" ::: "memory");
        }
        __syncthreads();

        const uint32_t base = sb + buf * S_STAGE;
        #pragma unroll
        for (int k16 = 0; k16 < 2; k16++) {
            uint32_t ah[4][4], bh[4][2];
            #pragma unroll
            for (int mi = 0; mi < 4; mi++) {
                uint32_t ra = base + (wm * 64 + mi * 16 + lrow) * 80 + k16 * 32 + lkb;
                ldsm4(ah[mi][0], ah[mi][1], ah[mi][2], ah[mi][3], ra);
            }
            #pragma unroll
            for (int p = 0; p < 2; p++) {
                uint32_t rb = base + S_TILE + (wn * 32 + p * 16 + lrow) * 80 + k16 * 32 + lkb;
                uint32_t r0, r1, r2, r3;
                ldsm4(r0, r1, r2, r3, rb);
                bh[2*p][0] = r0; bh[2*p+1][0] = r1; bh[2*p][1] = r2; bh[2*p+1][1] = r3;
            }
            #pragma unroll
            for (int mi = 0; mi < 4; mi++)
                #pragma unroll
                for (int ni = 0; ni < 4; ni++)
                    mma_f16(acc[mi][ni], ah[mi], bh[ni]);
        }
        __syncthreads();
    }

    float* outb = outs + (size_t)b * HW * HW;
    #pragma unroll
    for (int mi = 0; mi < 4; mi++) {
        int r0 = bm + wm * 64 + mi * 16 + (lane >> 2);
        #pragma unroll
        for (int ni = 0; ni < 4; ni++) {
            int col = bn + wn * 32 + ni * 8 + (lane & 3) * 2;
            #pragma unroll
            for (int half = 0; half < 2; half++) {
                int row = r0 + half * 8;
                float2 v = make_float2(acc[mi][ni][half * 2] * 0.0625f,
                                       acc[mi][ni][half * 2 + 1] * 0.0625f);
                *(float2*)&outb[(size_t)row * HW + col] = v;
            }
        }
    }
}

// ---------------- fp16 PV GEMM: 128x256 tile, trans-B, K=4096 ----------------
#define PV_A_B 10240
#define PV_BROW 528
#define PV_B_B (32 * PV_BROW)
#define PV_STAGE (PV_A_B + PV_B_B)
#define PV_SMEM (2 * PV_STAGE)

__global__ __launch_bounds__(256, 1)
void hmma_pv16(const __half* __restrict__ P, const __half* __restrict__ qkvt) {
    extern __shared__ char smem[];
    const uint32_t sb = smem_u32(smem);
    const int tid = threadIdx.x;
    const int wid = tid >> 5, lane = tid & 31;
    const int b = blockIdx.z;
    const int bm = blockIdx.y * 128;
    const int wm = wid & 1, wn = wid >> 1;

    const __half* A = P + (size_t)b * HW * HW + (size_t)bm * HW;
    const __half* B = qkvt + (size_t)b * HW * NQKV + 512;    // V rows [k][c]

    float acc[4][8][4];
    #pragma unroll
    for (int mi = 0; mi < 4; mi++)
        #pragma unroll
        for (int ni = 0; ni < 8; ni++)
            #pragma unroll
            for (int r = 0; r < 4; r++) acc[mi][ni][r] = 0.f;

    const int g = lane >> 3;
    const int lrow = (g & 1) * 8 + (lane & 7);
    const int lkb  = (g >> 1) * 16;

    auto load_stage = [&](int ks, int buf) {
        const uint32_t base = sb + buf * PV_STAGE;
        const int k0 = ks * 32;
        #pragma unroll
        for (int u = tid; u < 512; u += 256) {
            int row = u >> 2, c = u & 3;
            cp16(base + row * 80 + c * 16, A + (size_t)row * HW + k0 + c * 8);
        }
        #pragma unroll
        for (int u = tid; u < 1024; u += 256) {
            int row = u >> 5, c = u & 31;
            cp16(base + PV_A_B + row * PV_BROW + c * 16,
                 B + (size_t)(k0 + row) * NQKV + c * 8);
        }
    };

    load_stage(0, 0);
    asm volatile("cp.async.commit_group;" ::: "memory");

    const int ksteps = HW / 32;
    for (int ks = 0; ks < ksteps; ks++) {
        const int buf = ks & 1;
        if (ks + 1 < ksteps) {
            load_stage(ks + 1, buf ^ 1);
            asm volatile("cp.async.commit_group;" ::: "memory");
            asm volatile("cp.async.wait_group 1;" ::: "memory");
        } else {
            asm volatile("cp.async.wait_group 0;" ::: "memory");
        }
        __syncthreads();

        const uint32_t base = sb + buf * PV_STAGE;
        #pragma unroll
        for (int k16 = 0; k16 < 2; k16++) {
            uint32_t ah[4][4], bh[8][2];
            #pragma unroll
            for (int mi = 0; mi < 4; mi++) {
                uint32_t ra = base + (wm * 64 + mi * 16 + lrow) * 80 + k16 * 32 + lkb;
                ldsm4(ah[mi][0], ah[mi][1], ah[mi][2], ah[mi][3], ra);
            }
            #pragma unroll
            for (int p = 0; p < 4; p++) {
                int krl = k16 * 16 + (g & 1) * 8 + (lane & 7);
                int ncl = wn * 64 + p * 16 + (g >> 1) * 8;
                uint32_t rb = base + PV_A_B + krl * PV_BROW + ncl * 2;
                uint32_t r0, r1, r2, r3;
                ldsm4t(r0, r1, r2, r3, rb);
                bh[2*p][0] = r0; bh[2*p][1] = r1; bh[2*p+1][0] = r2; bh[2*p+1][1] = r3;
            }
            #pragma unroll
            for (int mi = 0; mi < 4; mi++)
                #pragma unroll
                for (int ni = 0; ni < 8; ni++)
                    mma_f16(acc[mi][ni], ah[mi], bh[ni]);
        }
        __syncthreads();
    }

    bf16* oh = g_at_h + (size_t)b * HW * CCH;
    bf16* ol = g_at_l + (size_t)b * HW * CCH;
    #pragma unroll
    for (int mi = 0; mi < 4; mi++) {
        int r0 = bm + wm * 64 + mi * 16 + (lane >> 2);
        #pragma unroll
        for (int ni = 0; ni < 8; ni++) {
            int col = wn * 64 + ni * 8 + (lane & 3) * 2;
            #pragma unroll
            for (int half = 0; half < 2; half++) {
                int row = r0 + half * 8;
                float v0 = acc[mi][ni][half * 2 + 0];
                float v1 = acc[mi][ni][half * 2 + 1];
                bf16 h0, l0, h1, l1;
                split2(v0, h0, l0); split2(v1, h1, l1);
                size_t o = (size_t)row * CCH + col;
                *(__nv_bfloat162*)(oh + o) = __nv_bfloat162(h0, h1);
                *(__nv_bfloat162*)(ol + o) = __nv_bfloat162(l0, l1);
            }
        }
    }
}

// ---------------- launch ----------------
extern "C" void kernel_launch(void* const* d_in, const int* in_sizes, int n_in,
                              void* d_out, int out_size) {
    const float* x     = (const float*)d_in[0];
    const float* gnw   = (const float*)d_in[1];
    const float* gnb   = (const float*)d_in[2];
    const float* qkvw  = (const float*)d_in[3];
    const float* qkvb  = (const float*)d_in[4];
    const float* projw = (const float*)d_in[5];
    const float* projb = (const float*)d_in[6];
    float* out = (float*)d_out;

    float* scores;
    __half *p16, *qkvt;
    bf16 *xnh, *xnl, *wqh, *wql, *wph, *wpl, *ath, *atl;
    cudaGetSymbolAddress((void**)&scores, g_scores);
    cudaGetSymbolAddress((void**)&p16, g_p16);
    cudaGetSymbolAddress((void**)&qkvt, g_qkvt);
    cudaGetSymbolAddress((void**)&xnh, g_xnt_h);
    cudaGetSymbolAddress((void**)&xnl, g_xnt_l);
    cudaGetSymbolAddress((void**)&wqh, g_wq_h);
    cudaGetSymbolAddress((void**)&wql, g_wq_l);
    cudaGetSymbolAddress((void**)&wph, g_wp_h);
    cudaGetSymbolAddress((void**)&wpl, g_wp_l);
    cudaGetSymbolAddress((void**)&ath, g_at_h);
    cudaGetSymbolAddress((void**)&atl, g_at_l);

    const size_t sNC = (size_t)HW * CCH;
    const size_t sQT = (size_t)HW * NQKV;
    const size_t sXN = (size_t)CCH * HW;

    cudaFuncSetAttribute((const void*)hmma128<CCH, CCH, NQKV, 1>,
                         cudaFuncAttributeMaxDynamicSharedMemorySize, HMMA_SMEM);
    cudaFuncSetAttribute((const void*)hmma128<CCH, CCH, HW, 2>,
                         cudaFuncAttributeMaxDynamicSharedMemorySize, HMMA_SMEM);
    cudaFuncSetAttribute((const void*)hmma_s16,
                         cudaFuncAttributeMaxDynamicSharedMemorySize, S_SMEM);
    cudaFuncSetAttribute((const void*)hmma_pv16,
                         cudaFuncAttributeMaxDynamicSharedMemorySize, PV_SMEM);

    // 1. GroupNorm (+ transpose + split)
    gn_stats<<<BATCH * NGROUPS, 256>>>(x);
    gn_apply_t<<<dim3(HW / 32, CCH / 32, BATCH), dim3(32, 8)>>>(x, gnw, gnb);

    // 2. weight splits
    w_split<<<(NQKV * CCH + 255) / 256, 256>>>(qkvw, wqh, wql, NQKV * CCH);
    w_split<<<(CCH * CCH + 255) / 256, 256>>>(projw, wph, wpl, CCH * CCH);

    // 3. qkvT fp16: M=4096, N=768, K=256 (bf16x3 accurate, fp16 storage)
    hmma128<CCH, CCH, NQKV, 1><<<dim3(NQKV / 128, HW / 128, BATCH), 256, HMMA_SMEM>>>(
        xnh, xnl, wqh, wql, nullptr, qkvt, qkvb, nullptr, 1.f, CCH / 32,
        sNC, 0, sQT, 0);

    // 4. scores = (1/16) Q K^T (fp16 single MMA)
    hmma_s16<<<dim3(HW / 128, HW / 128, BATCH), 256, S_SMEM>>>(qkvt, scores);

    // 5. softmax -> fp16 P
    softmax_p16<<<BATCH * HW, 256>>>();

    // 6. attn[q][c] = P . V (fp16 single MMA, trans-B), epilogue splits to bf16 h/l
    hmma_pv16<<<dim3(1, HW / 128, BATCH), 256, PV_SMEM>>>(p16, qkvt);

    // 7. out = x + W_proj attn + b (bf16x3)
    hmma128<CCH, CCH, HW, 2><<<dim3(HW / 128, CCH / 128, BATCH), 256, HMMA_SMEM>>>(
        wph, wpl, ath, atl, out, nullptr, projb, x, 1.f, CCH / 32,
        0, sNC, sXN, sXN);
}

// round 6
// speedup vs baseline: 5.1973x; 1.2603x over previous
#include <cuda_runtime.h>
#include <cuda_bf16.h>
#include <cuda_fp16.h>
#include <cstdint>

#define BATCH 4
#define CCH 256
#define HW 4096
#define NQKV 768
#define NGROUPS 16
#define EPS 1e-5f

typedef __nv_bfloat16 bf16;

// ---------------- scratch ----------------
__device__ __half g_qkvt[(size_t)BATCH * HW * NQKV];      // 24 MB fp16 [n][q|k|v]
__device__ float g_mean[BATCH * NGROUPS];
__device__ float g_rstd[BATCH * NGROUPS];
__device__ bf16 g_xnt_h[(size_t)BATCH * HW * CCH];
__device__ bf16 g_xnt_l[(size_t)BATCH * HW * CCH];
__device__ bf16 g_wq_h[NQKV * CCH];
__device__ bf16 g_wq_l[NQKV * CCH];
__device__ bf16 g_wp_h[CCH * CCH];
__device__ bf16 g_wp_l[CCH * CCH];
__device__ bf16 g_at_h[(size_t)BATCH * HW * CCH];
__device__ bf16 g_at_l[(size_t)BATCH * HW * CCH];

// ---------------- helpers ----------------
__device__ __forceinline__ uint32_t smem_u32(const void* p) {
    uint32_t a;
    asm("{ .reg .u64 t; cvta.to.shared.u64 t, %1; cvt.u32.u64 %0, t; }" : "=r"(a) : "l"(p));
    return a;
}
__device__ __forceinline__ void cp16(uint32_t s, const void* g) {
    asm volatile("cp.async.cg.shared.global [%0], [%1], 16;" :: "r"(s), "l"(g) : "memory");
}
__device__ __forceinline__ void ldsm4(uint32_t& r0, uint32_t& r1, uint32_t& r2, uint32_t& r3,
                                      uint32_t a) {
    asm volatile("ldmatrix.sync.aligned.m8n8.x4.shared.b16 {%0,%1,%2,%3}, [%4];"
                 : "=r"(r0), "=r"(r1), "=r"(r2), "=r"(r3) : "r"(a));
}
__device__ __forceinline__ void ldsm4t(uint32_t& r0, uint32_t& r1, uint32_t& r2, uint32_t& r3,
                                       uint32_t a) {
    asm volatile("ldmatrix.sync.aligned.m8n8.x4.trans.shared.b16 {%0,%1,%2,%3}, [%4];"
                 : "=r"(r0), "=r"(r1), "=r"(r2), "=r"(r3) : "r"(a));
}
__device__ __forceinline__ void mma_bf16(float* c, const uint32_t* a, const uint32_t* b) {
    asm volatile(
        "mma.sync.aligned.m16n8k16.row.col.f32.bf16.bf16.f32 "
        "{%0,%1,%2,%3}, {%4,%5,%6,%7}, {%8,%9}, {%0,%1,%2,%3};"
        : "+f"(c[0]), "+f"(c[1]), "+f"(c[2]), "+f"(c[3])
        : "r"(a[0]), "r"(a[1]), "r"(a[2]), "r"(a[3]), "r"(b[0]), "r"(b[1]));
}
__device__ __forceinline__ void mma_f16(float* c, const uint32_t* a, const uint32_t* b) {
    asm volatile(
        "mma.sync.aligned.m16n8k16.row.col.f32.f16.f16.f32 "
        "{%0,%1,%2,%3}, {%4,%5,%6,%7}, {%8,%9}, {%0,%1,%2,%3};"
        : "+f"(c[0]), "+f"(c[1]), "+f"(c[2]), "+f"(c[3])
        : "r"(a[0]), "r"(a[1]), "r"(a[2]), "r"(a[3]), "r"(b[0]), "r"(b[1]));
}
__device__ __forceinline__ void split2(float v, bf16& h, bf16& l) {
    h = __float2bfloat16_rn(v);
    l = __float2bfloat16_rn(v - __bfloat162float(h));
}

// ---------------- GroupNorm ----------------
__global__ void gn_stats(const float* __restrict__ x) {
    int bg = blockIdx.x;
    const float4* p = (const float4*)(x + (size_t)bg * 16 * HW);
    float s = 0.f, sq = 0.f;
    for (int i = threadIdx.x; i < 16384; i += 256) {
        float4 v = p[i];
        s  += v.x + v.y + v.z + v.w;
        sq += v.x*v.x + v.y*v.y + v.z*v.z + v.w*v.w;
    }
    __shared__ float ss[256], sz[256];
    ss[threadIdx.x] = s; sz[threadIdx.x] = sq;
    __syncthreads();
    for (int o = 128; o > 0; o >>= 1) {
        if (threadIdx.x < o) { ss[threadIdx.x] += ss[threadIdx.x + o]; sz[threadIdx.x] += sz[threadIdx.x + o]; }
        __syncthreads();
    }
    if (threadIdx.x == 0) {
        float m = ss[0] * (1.f / 65536.f);
        float v = sz[0] * (1.f / 65536.f) - m * m;
        g_mean[bg] = m;
        g_rstd[bg] = rsqrtf(v + EPS);
    }
}

__global__ void gn_apply_t(const float* __restrict__ x, const float* __restrict__ w,
                           const float* __restrict__ bgn) {
    __shared__ float t[32][33];
    int b = blockIdx.z;
    int n0 = blockIdx.x * 32, c0 = blockIdx.y * 32;
    int tx = threadIdx.x, ty = threadIdx.y;
    const float* src = x + (size_t)b * CCH * HW;
    #pragma unroll
    for (int j = 0; j < 4; j++) {
        int c = c0 + ty + j * 8;
        int bg = b * NGROUPS + (c >> 4);
        float sc = g_rstd[bg] * w[c];
        float sh = bgn[c] - g_mean[bg] * sc;
        t[ty + j * 8][tx] = src[(size_t)c * HW + n0 + tx] * sc + sh;
    }
    __syncthreads();
    bf16* dh = g_xnt_h + (size_t)b * HW * CCH;
    bf16* dl = g_xnt_l + (size_t)b * HW * CCH;
    #pragma unroll
    for (int j = 0; j < 4; j++) {
        float v = t[tx][ty + j * 8];
        bf16 h, l; split2(v, h, l);
        size_t o = (size_t)(n0 + ty + j * 8) * CCH + c0 + tx;
        dh[o] = h; dl[o] = l;
    }
}

__global__ void w_split(const float* __restrict__ w, bf16* __restrict__ h,
                        bf16* __restrict__ l, int n) {
    int i = blockIdx.x * 256 + threadIdx.x;
    if (i < n) {
        bf16 hh, ll; split2(w[i], hh, ll);
        h[i] = hh; l[i] = ll;
    }
}

// ---------------- HMMA bf16x3 GEMM, 128x128 tile (qkv EPI1->fp16 out, proj EPI2) ----------------
#define TILE_B 10240
#define STAGE_B 40960
#define HMMA_SMEM (2 * STAGE_B)

template<int ASTR, int BSTR, int OSTR, int EPI>
__global__ __launch_bounds__(256, 1)
void hmma128(const bf16* __restrict__ Ah_, const bf16* __restrict__ Al_,
             const bf16* __restrict__ Bh_, const bf16* __restrict__ Bl_,
             float* __restrict__ outf, __half* __restrict__ outh,
             const float* __restrict__ bias, const float* __restrict__ resid,
             float alpha, int ksteps, size_t aB, size_t bB, size_t oB, size_t rB) {
    extern __shared__ char smem[];
    const uint32_t sb = smem_u32(smem);
    const int tid = threadIdx.x;
    const int wid = tid >> 5, lane = tid & 31;
    const int b = blockIdx.z;
    const int bm = blockIdx.y * 128;
    const int bn = blockIdx.x * 128;
    const int wm = wid & 1, wn = wid >> 1;

    const bf16* Ah = Ah_ + (size_t)b * aB + (size_t)bm * ASTR;
    const bf16* Al = Al_ + (size_t)b * aB + (size_t)bm * ASTR;
    const bf16* Bh = Bh_ + (size_t)b * bB + (size_t)bn * BSTR;
    const bf16* Bl = Bl_ + (size_t)b * bB + (size_t)bn * BSTR;

    const int u0row = tid >> 2, u0c = tid & 3;
    const int u1row = (tid + 256) >> 2, u1c = (tid + 256) & 3;

    float acc[4][4][4];
    #pragma unroll
    for (int mi = 0; mi < 4; mi++)
        #pragma unroll
        for (int ni = 0; ni < 4; ni++)
            #pragma unroll
            for (int r = 0; r < 4; r++) acc[mi][ni][r] = 0.f;

    const int g = lane >> 3;
    const int lrow = (g & 1) * 8 + (lane & 7);
    const int lkb  = (g >> 1) * 16;

    auto load_stage = [&](int ks, int buf) {
        const uint32_t base = sb + buf * STAGE_B;
        const int k0 = ks * 32;
        uint32_t so0 = base + u0row * 80 + u0c * 16;
        uint32_t so1 = base + u1row * 80 + u1c * 16;
        size_t ga0 = (size_t)u0row * ASTR + k0 + u0c * 8;
        size_t ga1 = (size_t)u1row * ASTR + k0 + u1c * 8;
        size_t gb0 = (size_t)u0row * BSTR + k0 + u0c * 8;
        size_t gb1 = (size_t)u1row * BSTR + k0 + u1c * 8;
        cp16(so0,              Ah + ga0);
        cp16(so1,              Ah + ga1);
        cp16(so0 + TILE_B,     Al + ga0);
        cp16(so1 + TILE_B,     Al + ga1);
        cp16(so0 + 2 * TILE_B, Bh + gb0);
        cp16(so1 + 2 * TILE_B, Bh + gb1);
        cp16(so0 + 3 * TILE_B, Bl + gb0);
        cp16(so1 + 3 * TILE_B, Bl + gb1);
    };

    load_stage(0, 0);
    asm volatile("cp.async.commit_group;" ::: "memory");

    for (int ks = 0; ks < ksteps; ks++) {
        const int buf = ks & 1;
        if (ks + 1 < ksteps) {
            load_stage(ks + 1, buf ^ 1);
            asm volatile("cp.async.commit_group;" ::: "memory");
            asm volatile("cp.async.wait_group 1;" ::: "memory");
        } else {
            asm volatile("cp.async.wait_group 0;" ::: "memory");
        }
        __syncthreads();

        const uint32_t base = sb + buf * STAGE_B;
        #pragma unroll
        for (int k16 = 0; k16 < 2; k16++) {
            uint32_t ah[4][4], al[4][4], bh[4][2], bl[4][2];
            #pragma unroll
            for (int mi = 0; mi < 4; mi++) {
                uint32_t ra = base + (wm * 64 + mi * 16 + lrow) * 80 + k16 * 32 + lkb;
                ldsm4(ah[mi][0], ah[mi][1], ah[mi][2], ah[mi][3], ra);
                ldsm4(al[mi][0], al[mi][1], al[mi][2], al[mi][3], ra + TILE_B);
            }
            #pragma unroll
            for (int p = 0; p < 2; p++) {
                uint32_t rb = base + 2 * TILE_B + (wn * 32 + p * 16 + lrow) * 80 + k16 * 32 + lkb;
                uint32_t r0, r1, r2, r3;
                ldsm4(r0, r1, r2, r3, rb);
                bh[2*p][0] = r0; bh[2*p+1][0] = r1; bh[2*p][1] = r2; bh[2*p+1][1] = r3;
                ldsm4(r0, r1, r2, r3, rb + TILE_B);
                bl[2*p][0] = r0; bl[2*p+1][0] = r1; bl[2*p][1] = r2; bl[2*p+1][1] = r3;
            }
            #pragma unroll
            for (int mi = 0; mi < 4; mi++)
                #pragma unroll
                for (int ni = 0; ni < 4; ni++) {
                    mma_bf16(acc[mi][ni], ah[mi], bh[ni]);
                    mma_bf16(acc[mi][ni], ah[mi], bl[ni]);
                    mma_bf16(acc[mi][ni], al[mi], bh[ni]);
                }
        }
        __syncthreads();
    }

    #pragma unroll
    for (int mi = 0; mi < 4; mi++) {
        int r0 = bm + wm * 64 + mi * 16 + (lane >> 2);
        #pragma unroll
        for (int ni = 0; ni < 4; ni++) {
            int col = bn + wn * 32 + ni * 8 + (lane & 3) * 2;
            #pragma unroll
            for (int half = 0; half < 2; half++) {
                int row = r0 + half * 8;
                float v0 = acc[mi][ni][half * 2 + 0];
                float v1 = acc[mi][ni][half * 2 + 1];
                if (EPI == 1) {
                    v0 += bias[col]; v1 += bias[col + 1];
                    size_t o = (size_t)b * oB + (size_t)row * OSTR + col;
                    *(__half2*)(outh + o) = __floats2half2_rn(v0, v1);
                } else {
                    size_t o = (size_t)b * oB + (size_t)row * OSTR + col;
                    const float* rp = resid + (size_t)b * rB + (size_t)row * OSTR + col;
                    float bv = bias[row];
                    float2 r = *(const float2*)rp;
                    *(float2*)(outf + o) = make_float2(v0 + bv + r.x, v1 + bv + r.y);
                }
            }
        }
    }
}

// ---------------- fused flash attention: scores + softmax + PV ----------------
// CTA: 128 Q rows; 8 warps x 16 rows (exclusive). KV streamed in 64-row blocks.
#define QR 128
#define KB 64
#define QSTRIDE 528
#define Q_BYTES (QR * QSTRIDE)            // 67584
#define KV_ROW 528
#define K_BYTES (KB * KV_ROW)             // 33792
#define FA_STAGE (2 * K_BYTES)            // 67584
#define FA_SMEM (Q_BYTES + 2 * FA_STAGE)  // 202752

__global__ __launch_bounds__(256, 1)
void flash_attn(const __half* __restrict__ qkvt) {
    extern __shared__ char smem[];
    const uint32_t sb = smem_u32(smem);
    const int tid = threadIdx.x;
    const int wid = tid >> 5, lane = tid & 31;
    const int b = blockIdx.y;
    const int bm = blockIdx.x * QR;
    const __half* base = qkvt + (size_t)b * HW * NQKV;

    const uint32_t sQ = sb;
    const uint32_t sK0 = sb + Q_BYTES;

    // Q load (grouped with KV stage 0)
    #pragma unroll
    for (int j = 0; j < 16; j++) {
        int u = tid + 256 * j;
        int row = u >> 5, c = u & 31;
        cp16(sQ + row * QSTRIDE + c * 16, base + (size_t)(bm + row) * NQKV + c * 8);
    }
    auto load_kv = [&](int ks, int buf) {
        const uint32_t st = sK0 + buf * FA_STAGE;
        #pragma unroll
        for (int j = 0; j < 8; j++) {
            int u = tid + 256 * j;
            int row = u >> 5, c = u & 31;
            const __half* gp = base + (size_t)(ks * KB + row) * NQKV + c * 8;
            cp16(st + row * KV_ROW + c * 16,           gp + 256);  // K
            cp16(st + K_BYTES + row * KV_ROW + c * 16, gp + 512);  // V
        }
    };
    load_kv(0, 0);
    asm volatile("cp.async.commit_group;" ::: "memory");
    load_kv(1, 1);
    asm volatile("cp.async.commit_group;" ::: "memory");

    float O[32][4];
    #pragma unroll
    for (int nt = 0; nt < 32; nt++)
        #pragma unroll
        for (int r = 0; r < 4; r++) O[nt][r] = 0.f;
    float m0 = -1e30f, m1 = -1e30f, l0 = 0.f, l1 = 0.f;

    const int g = lane >> 3;
    const int lrow = (g & 1) * 8 + (lane & 7);
    const int lkb = (g >> 1) * 16;
    const float c1 = 0.0625f * 1.44269504f;   // log2(e)/16

    const int NITER = HW / KB;
    for (int it = 0; it < NITER; it++) {
        const int buf = it & 1;
        if (it + 1 < NITER)
            asm volatile("cp.async.wait_group 1;" ::: "memory");
        else
            asm volatile("cp.async.wait_group 0;" ::: "memory");
        __syncthreads();

        const uint32_t sK = sK0 + buf * FA_STAGE;
        const uint32_t sV = sK + K_BYTES;

        // ---- S = Q K^T : warp tile 16 x 64 ----
        float S[8][4];
        #pragma unroll
        for (int nt = 0; nt < 8; nt++)
            #pragma unroll
            for (int r = 0; r < 4; r++) S[nt][r] = 0.f;

        #pragma unroll
        for (int k16 = 0; k16 < 16; k16++) {
            uint32_t a[4];
            ldsm4(a[0], a[1], a[2], a[3],
                  sQ + (wid * 16 + lrow) * QSTRIDE + k16 * 32 + lkb);
            uint32_t kb[8][2];
            #pragma unroll
            for (int p = 0; p < 4; p++) {
                uint32_t r0, r1, r2, r3;
                ldsm4(r0, r1, r2, r3, sK + (p * 16 + lrow) * KV_ROW + k16 * 32 + lkb);
                kb[2*p][0] = r0; kb[2*p+1][0] = r1;
                kb[2*p][1] = r2; kb[2*p+1][1] = r3;
            }
            #pragma unroll
            for (int nt = 0; nt < 8; nt++)
                mma_f16(S[nt], a, kb[nt]);
        }

        // ---- online softmax (thread rows: r = lane>>2 and r+8) ----
        float mx0 = -1e30f, mx1 = -1e30f;
        #pragma unroll
        for (int nt = 0; nt < 8; nt++) {
            mx0 = fmaxf(mx0, fmaxf(S[nt][0], S[nt][1]));
            mx1 = fmaxf(mx1, fmaxf(S[nt][2], S[nt][3]));
        }
        mx0 = fmaxf(mx0, __shfl_xor_sync(0xffffffffu, mx0, 1));
        mx0 = fmaxf(mx0, __shfl_xor_sync(0xffffffffu, mx0, 2));
        mx1 = fmaxf(mx1, __shfl_xor_sync(0xffffffffu, mx1, 1));
        mx1 = fmaxf(mx1, __shfl_xor_sync(0xffffffffu, mx1, 2));
        float nm0 = fmaxf(m0, mx0), nm1 = fmaxf(m1, mx1);
        float a0 = exp2f((m0 - nm0) * c1), a1 = exp2f((m1 - nm1) * c1);
        m0 = nm0; m1 = nm1;
        float rs0 = 0.f, rs1 = 0.f;
        #pragma unroll
        for (int nt = 0; nt < 8; nt++) {
            S[nt][0] = exp2f((S[nt][0] - m0) * c1);
            S[nt][1] = exp2f((S[nt][1] - m0) * c1);
            S[nt][2] = exp2f((S[nt][2] - m1) * c1);
            S[nt][3] = exp2f((S[nt][3] - m1) * c1);
            rs0 += S[nt][0] + S[nt][1];
            rs1 += S[nt][2] + S[nt][3];
        }
        if (!__all_sync(0xffffffffu, (a0 == 1.f) && (a1 == 1.f))) {
            #pragma unroll
            for (int nt = 0; nt < 32; nt++) {
                O[nt][0] *= a0; O[nt][1] *= a0;
                O[nt][2] *= a1; O[nt][3] *= a1;
            }
            l0 *= a0; l1 *= a1;
        }
        l0 += rs0; l1 += rs1;

        // ---- O += P V (P a-frags straight from S regs; V via trans ldsm) ----
        #pragma unroll
        for (int k16 = 0; k16 < 4; k16++) {
            uint32_t pa[4];
            __half2 hh;
            hh = __floats2half2_rn(S[2*k16][0],   S[2*k16][1]);   pa[0] = *(uint32_t*)&hh;
            hh = __floats2half2_rn(S[2*k16][2],   S[2*k16][3]);   pa[1] = *(uint32_t*)&hh;
            hh = __floats2half2_rn(S[2*k16+1][0], S[2*k16+1][1]); pa[2] = *(uint32_t*)&hh;
            hh = __floats2half2_rn(S[2*k16+1][2], S[2*k16+1][3]); pa[3] = *(uint32_t*)&hh;
            int krl = k16 * 16 + (g & 1) * 8 + (lane & 7);
            #pragma unroll
            for (int p = 0; p < 16; p++) {
                int ncl = p * 16 + (g >> 1) * 8;
                uint32_t r0, r1, r2, r3;
                ldsm4t(r0, r1, r2, r3, sV + krl * KV_ROW + ncl * 2);
                uint32_t vb0[2] = {r0, r1};
                uint32_t vb1[2] = {r2, r3};
                mma_f16(O[2*p],     pa, vb0);
                mma_f16(O[2*p + 1], pa, vb1);
            }
        }
        __syncthreads();
        if (it + 2 < NITER) {
            load_kv(it + 2, buf);
            asm volatile("cp.async.commit_group;" ::: "memory");
        }
    }

    // ---- epilogue: normalize, split to bf16 h/l ----
    l0 += __shfl_xor_sync(0xffffffffu, l0, 1);
    l0 += __shfl_xor_sync(0xffffffffu, l0, 2);
    l1 += __shfl_xor_sync(0xffffffffu, l1, 1);
    l1 += __shfl_xor_sync(0xffffffffu, l1, 2);
    float inv0 = 1.f / l0, inv1 = 1.f / l1;

    bf16* oh = g_at_h + (size_t)b * HW * CCH;
    bf16* ol = g_at_l + (size_t)b * HW * CCH;
    int row0 = bm + wid * 16 + (lane >> 2);
    #pragma unroll
    for (int nt = 0; nt < 32; nt++) {
        int col = nt * 8 + (lane & 3) * 2;
        float v0 = O[nt][0] * inv0, v1 = O[nt][1] * inv0;
        float v2 = O[nt][2] * inv1, v3 = O[nt][3] * inv1;
        bf16 h0, lo0, h1, lo1;
        split2(v0, h0, lo0); split2(v1, h1, lo1);
        size_t o = (size_t)row0 * CCH + col;
        *(__nv_bfloat162*)(oh + o) = __nv_bfloat162(h0, h1);
        *(__nv_bfloat162*)(ol + o) = __nv_bfloat162(lo0, lo1);
        split2(v2, h0, lo0); split2(v3, h1, lo1);
        o = (size_t)(row0 + 8) * CCH + col;
        *(__nv_bfloat162*)(oh + o) = __nv_bfloat162(h0, h1);
        *(__nv_bfloat162*)(ol + o) = __nv_bfloat162(lo0, lo1);
    }
}

// ---------------- launch ----------------
extern "C" void kernel_launch(void* const* d_in, const int* in_sizes, int n_in,
                              void* d_out, int out_size) {
    const float* x     = (const float*)d_in[0];
    const float* gnw   = (const float*)d_in[1];
    const float* gnb   = (const float*)d_in[2];
    const float* qkvw  = (const float*)d_in[3];
    const float* qkvb  = (const float*)d_in[4];
    const float* projw = (const float*)d_in[5];
    const float* projb = (const float*)d_in[6];
    float* out = (float*)d_out;

    __half* qkvt;
    bf16 *xnh, *xnl, *wqh, *wql, *wph, *wpl, *ath, *atl;
    cudaGetSymbolAddress((void**)&qkvt, g_qkvt);
    cudaGetSymbolAddress((void**)&xnh, g_xnt_h);
    cudaGetSymbolAddress((void**)&xnl, g_xnt_l);
    cudaGetSymbolAddress((void**)&wqh, g_wq_h);
    cudaGetSymbolAddress((void**)&wql, g_wq_l);
    cudaGetSymbolAddress((void**)&wph, g_wp_h);
    cudaGetSymbolAddress((void**)&wpl, g_wp_l);
    cudaGetSymbolAddress((void**)&ath, g_at_h);
    cudaGetSymbolAddress((void**)&atl, g_at_l);

    const size_t sNC = (size_t)HW * CCH;
    const size_t sQT = (size_t)HW * NQKV;
    const size_t sXN = (size_t)CCH * HW;

    cudaFuncSetAttribute((const void*)hmma128<CCH, CCH, NQKV, 1>,
                         cudaFuncAttributeMaxDynamicSharedMemorySize, HMMA_SMEM);
    cudaFuncSetAttribute((const void*)hmma128<CCH, CCH, HW, 2>,
                         cudaFuncAttributeMaxDynamicSharedMemorySize, HMMA_SMEM);
    cudaFuncSetAttribute((const void*)flash_attn,
                         cudaFuncAttributeMaxDynamicSharedMemorySize, FA_SMEM);

    // 1. GroupNorm (+ transpose + split)
    gn_stats<<<BATCH * NGROUPS, 256>>>(x);
    gn_apply_t<<<dim3(HW / 32, CCH / 32, BATCH), dim3(32, 8)>>>(x, gnw, gnb);

    // 2. weight splits
    w_split<<<(NQKV * CCH + 255) / 256, 256>>>(qkvw, wqh, wql, NQKV * CCH);
    w_split<<<(CCH * CCH + 255) / 256, 256>>>(projw, wph, wpl, CCH * CCH);

    // 3. qkvT fp16: M=4096, N=768, K=256 (bf16x3 accurate, fp16 storage)
    hmma128<CCH, CCH, NQKV, 1><<<dim3(NQKV / 128, HW / 128, BATCH), 256, HMMA_SMEM>>>(
        xnh, xnl, wqh, wql, nullptr, qkvt, qkvb, nullptr, 1.f, CCH / 32,
        sNC, 0, sQT, 0);

    // 4-6. fused flash attention -> attn bf16 h/l
    flash_attn<<<dim3(HW / QR, BATCH), 256, FA_SMEM>>>(qkvt);

    // 7. out = x + W_proj attn + b (bf16x3)
    hmma128<CCH, CCH, HW, 2><<<dim3(HW / 128, CCH / 128, BATCH), 256, HMMA_SMEM>>>(
        wph, wpl, ath, atl, out, nullptr, projb, x, 1.f, CCH / 32,
        0, sNC, sXN, sXN);
}

// round 7
// speedup vs baseline: 5.5770x; 1.0730x over previous
#include <cuda_runtime.h>
#include <cuda_bf16.h>
#include <cuda_fp16.h>
#include <cstdint>

#define BATCH 4
#define CCH 256
#define HW 4096
#define NQKV 768
#define NGROUPS 16
#define EPS 1e-5f

typedef __nv_bfloat16 bf16;

// ---------------- scratch ----------------
__device__ __half g_qkvt[(size_t)BATCH * HW * NQKV];      // 24 MB fp16 [n][q|k|v]
__device__ __half g_xn16[(size_t)BATCH * HW * CCH];       // 8 MB fp16 xn^T [n][c]
__device__ __half g_wq16[NQKV * CCH];                     // fp16 qkv weights
__device__ float g_mean[BATCH * NGROUPS];
__device__ float g_rstd[BATCH * NGROUPS];
__device__ bf16 g_wp_h[CCH * CCH];
__device__ bf16 g_wp_l[CCH * CCH];
__device__ bf16 g_at_h[(size_t)BATCH * HW * CCH];
__device__ bf16 g_at_l[(size_t)BATCH * HW * CCH];

// ---------------- helpers ----------------
__device__ __forceinline__ uint32_t smem_u32(const void* p) {
    uint32_t a;
    asm("{ .reg .u64 t; cvta.to.shared.u64 t, %1; cvt.u32.u64 %0, t; }" : "=r"(a) : "l"(p));
    return a;
}
__device__ __forceinline__ void cp16(uint32_t s, const void* g) {
    asm volatile("cp.async.cg.shared.global [%0], [%1], 16;" :: "r"(s), "l"(g) : "memory");
}
__device__ __forceinline__ void ldsm4(uint32_t& r0, uint32_t& r1, uint32_t& r2, uint32_t& r3,
                                      uint32_t a) {
    asm volatile("ldmatrix.sync.aligned.m8n8.x4.shared.b16 {%0,%1,%2,%3}, [%4];"
                 : "=r"(r0), "=r"(r1), "=r"(r2), "=r"(r3) : "r"(a));
}
__device__ __forceinline__ void ldsm4t(uint32_t& r0, uint32_t& r1, uint32_t& r2, uint32_t& r3,
                                       uint32_t a) {
    asm volatile("ldmatrix.sync.aligned.m8n8.x4.trans.shared.b16 {%0,%1,%2,%3}, [%4];"
                 : "=r"(r0), "=r"(r1), "=r"(r2), "=r"(r3) : "r"(a));
}
__device__ __forceinline__ void mma_bf16(float* c, const uint32_t* a, const uint32_t* b) {
    asm volatile(
        "mma.sync.aligned.m16n8k16.row.col.f32.bf16.bf16.f32 "
        "{%0,%1,%2,%3}, {%4,%5,%6,%7}, {%8,%9}, {%0,%1,%2,%3};"
        : "+f"(c[0]), "+f"(c[1]), "+f"(c[2]), "+f"(c[3])
        : "r"(a[0]), "r"(a[1]), "r"(a[2]), "r"(a[3]), "r"(b[0]), "r"(b[1]));
}
__device__ __forceinline__ void mma_f16(float* c, const uint32_t* a, const uint32_t* b) {
    asm volatile(
        "mma.sync.aligned.m16n8k16.row.col.f32.f16.f16.f32 "
        "{%0,%1,%2,%3}, {%4,%5,%6,%7}, {%8,%9}, {%0,%1,%2,%3};"
        : "+f"(c[0]), "+f"(c[1]), "+f"(c[2]), "+f"(c[3])
        : "r"(a[0]), "r"(a[1]), "r"(a[2]), "r"(a[3]), "r"(b[0]), "r"(b[1]));
}
__device__ __forceinline__ void split2(float v, bf16& h, bf16& l) {
    h = __float2bfloat16_rn(v);
    l = __float2bfloat16_rn(v - __bfloat162float(h));
}
#define MBAR_INIT(addr, cnt) \
    asm volatile("mbarrier.init.shared.b64 [%0], %1;" :: "r"(addr), "r"(cnt) : "memory")
#define MBAR_ARRIVE(addr) \
    asm volatile("mbarrier.arrive.shared.b64 _, [%0];" :: "r"(addr) : "memory")
#define MBAR_WAIT(addr, phase) do {                                              \
    uint32_t _m = (addr); uint32_t _p = (phase); uint32_t _d;                    \
    asm volatile("{\n\t.reg .pred P;\n\t"                                        \
        "mbarrier.try_wait.parity.acquire.cta.shared::cta.b64 P, [%1], %2;\n\t"  \
        "selp.b32 %0, 1, 0, P;\n\t}" : "=r"(_d) : "r"(_m), "r"(_p) : "memory");  \
    if (!_d) {                                                                   \
        asm volatile("{\n\t.reg .pred P1;\n\t"                                   \
        "W_%=:\n\t"                                                              \
        "mbarrier.try_wait.parity.acquire.cta.shared::cta.b64 P1, [%0], %1, 0x989680;\n\t" \
        "@P1 bra.uni D_%=;\n\tbra.uni W_%=;\n\tD_%=:\n\t}"                       \
        :: "r"(_m), "r"(_p) : "memory");                                         \
    } } while (0)

// ---------------- GroupNorm ----------------
__global__ void gn_stats(const float* __restrict__ x) {
    int bg = blockIdx.x;
    const float4* p = (const float4*)(x + (size_t)bg * 16 * HW);
    float s = 0.f, sq = 0.f;
    for (int i = threadIdx.x; i < 16384; i += 256) {
        float4 v = p[i];
        s  += v.x + v.y + v.z + v.w;
        sq += v.x*v.x + v.y*v.y + v.z*v.z + v.w*v.w;
    }
    __shared__ float ss[256], sz[256];
    ss[threadIdx.x] = s; sz[threadIdx.x] = sq;
    __syncthreads();
    for (int o = 128; o > 0; o >>= 1) {
        if (threadIdx.x < o) { ss[threadIdx.x] += ss[threadIdx.x + o]; sz[threadIdx.x] += sz[threadIdx.x + o]; }
        __syncthreads();
    }
    if (threadIdx.x == 0) {
        float m = ss[0] * (1.f / 65536.f);
        float v = sz[0] * (1.f / 65536.f) - m * m;
        g_mean[bg] = m;
        g_rstd[bg] = rsqrtf(v + EPS);
    }
}

// GroupNorm apply + transpose -> fp16 xn^T [b][n][c]
__global__ void gn_apply_t(const float* __restrict__ x, const float* __restrict__ w,
                           const float* __restrict__ bgn) {
    __shared__ float t[32][33];
    int b = blockIdx.z;
    int n0 = blockIdx.x * 32, c0 = blockIdx.y * 32;
    int tx = threadIdx.x, ty = threadIdx.y;
    const float* src = x + (size_t)b * CCH * HW;
    #pragma unroll
    for (int j = 0; j < 4; j++) {
        int c = c0 + ty + j * 8;
        int bg = b * NGROUPS + (c >> 4);
        float sc = g_rstd[bg] * w[c];
        float sh = bgn[c] - g_mean[bg] * sc;
        t[ty + j * 8][tx] = src[(size_t)c * HW + n0 + tx] * sc + sh;
    }
    __syncthreads();
    __half* d = g_xn16 + (size_t)b * HW * CCH;
    #pragma unroll
    for (int j = 0; j < 4; j++) {
        float v = t[tx][ty + j * 8];
        d[(size_t)(n0 + ty + j * 8) * CCH + c0 + tx] = __float2half_rn(v);
    }
}

__global__ void w16(const float* __restrict__ w, __half* __restrict__ o, int n) {
    int i = blockIdx.x * 256 + threadIdx.x;
    if (i < n) o[i] = __float2half_rn(w[i]);
}
__global__ void w_split(const float* __restrict__ w, bf16* __restrict__ h,
                        bf16* __restrict__ l, int n) {
    int i = blockIdx.x * 256 + threadIdx.x;
    if (i < n) {
        bf16 hh, ll; split2(w[i], hh, ll);
        h[i] = hh; l[i] = ll;
    }
}

// ---------------- fp16 qkv GEMM: out[n][768] = xn[n][:] . Wq[o][:] + b[o] ----------------
#define QK_TILE 10240
#define QK_STAGE 20480
#define QK_SMEM (2 * QK_STAGE)

__global__ __launch_bounds__(256, 2)
void hmma_qkv(const __half* __restrict__ A_, const __half* __restrict__ Wq,
              const float* __restrict__ bias, __half* __restrict__ out) {
    extern __shared__ char smem[];
    const uint32_t sb = smem_u32(smem);
    const int tid = threadIdx.x;
    const int wid = tid >> 5, lane = tid & 31;
    const int b = blockIdx.z;
    const int bm = blockIdx.y * 128;
    const int bn = blockIdx.x * 128;
    const int wm = wid & 1, wn = wid >> 1;

    const __half* A = A_ + (size_t)b * HW * CCH + (size_t)bm * CCH;
    const __half* B = Wq + (size_t)bn * CCH;

    const int u0row = tid >> 2, u0c = tid & 3;
    const int u1row = (tid + 256) >> 2, u1c = (tid + 256) & 3;

    float acc[4][4][4];
    #pragma unroll
    for (int mi = 0; mi < 4; mi++)
        #pragma unroll
        for (int ni = 0; ni < 4; ni++)
            #pragma unroll
            for (int r = 0; r < 4; r++) acc[mi][ni][r] = 0.f;

    const int g = lane >> 3;
    const int lrow = (g & 1) * 8 + (lane & 7);
    const int lkb  = (g >> 1) * 16;

    auto load_stage = [&](int ks, int buf) {
        const uint32_t base = sb + buf * QK_STAGE;
        const int k0 = ks * 32;
        uint32_t so0 = base + u0row * 80 + u0c * 16;
        uint32_t so1 = base + u1row * 80 + u1c * 16;
        cp16(so0,           A + (size_t)u0row * CCH + k0 + u0c * 8);
        cp16(so1,           A + (size_t)u1row * CCH + k0 + u1c * 8);
        cp16(so0 + QK_TILE, B + (size_t)u0row * CCH + k0 + u0c * 8);
        cp16(so1 + QK_TILE, B + (size_t)u1row * CCH + k0 + u1c * 8);
    };

    load_stage(0, 0);
    asm volatile("cp.async.commit_group;" ::: "memory");

    const int ksteps = CCH / 32;
    for (int ks = 0; ks < ksteps; ks++) {
        const int buf = ks & 1;
        if (ks + 1 < ksteps) {
            load_stage(ks + 1, buf ^ 1);
            asm volatile("cp.async.commit_group;" ::: "memory");
            asm volatile("cp.async.wait_group 1;" ::: "memory");
        } else {
            asm volatile("cp.async.wait_group 0;" ::: "memory");
        }
        __syncthreads();

        const uint32_t base = sb + buf * QK_STAGE;
        #pragma unroll
        for (int k16 = 0; k16 < 2; k16++) {
            uint32_t ah[4][4], bh[4][2];
            #pragma unroll
            for (int mi = 0; mi < 4; mi++) {
                uint32_t ra = base + (wm * 64 + mi * 16 + lrow) * 80 + k16 * 32 + lkb;
                ldsm4(ah[mi][0], ah[mi][1], ah[mi][2], ah[mi][3], ra);
            }
            #pragma unroll
            for (int p = 0; p < 2; p++) {
                uint32_t rb = base + QK_TILE + (wn * 32 + p * 16 + lrow) * 80 + k16 * 32 + lkb;
                uint32_t r0, r1, r2, r3;
                ldsm4(r0, r1, r2, r3, rb);
                bh[2*p][0] = r0; bh[2*p+1][0] = r1; bh[2*p][1] = r2; bh[2*p+1][1] = r3;
            }
            #pragma unroll
            for (int mi = 0; mi < 4; mi++)
                #pragma unroll
                for (int ni = 0; ni < 4; ni++)
                    mma_f16(acc[mi][ni], ah[mi], bh[ni]);
        }
        __syncthreads();
    }

    __half* outb = out + (size_t)b * HW * NQKV;
    #pragma unroll
    for (int mi = 0; mi < 4; mi++) {
        int r0 = bm + wm * 64 + mi * 16 + (lane >> 2);
        #pragma unroll
        for (int ni = 0; ni < 4; ni++) {
            int col = bn + wn * 32 + ni * 8 + (lane & 3) * 2;
            float b0 = bias[col], b1 = bias[col + 1];
            #pragma unroll
            for (int half = 0; half < 2; half++) {
                int row = r0 + half * 8;
                *(__half2*)(outb + (size_t)row * NQKV + col) =
                    __floats2half2_rn(acc[mi][ni][half * 2] + b0,
                                      acc[mi][ni][half * 2 + 1] + b1);
            }
        }
    }
}

// ---------------- HMMA bf16x3 proj GEMM (EPI: bias[row] + resid) ----------------
#define TILE_B 10240
#define STAGE_B 40960
#define HMMA_SMEM (2 * STAGE_B)

__global__ __launch_bounds__(256, 1)
void hmma_proj(const bf16* __restrict__ Ah_, const bf16* __restrict__ Al_,
               const bf16* __restrict__ Bh_, const bf16* __restrict__ Bl_,
               float* __restrict__ outf, const float* __restrict__ bias,
               const float* __restrict__ resid) {
    extern __shared__ char smem[];
    const uint32_t sb = smem_u32(smem);
    const int tid = threadIdx.x;
    const int wid = tid >> 5, lane = tid & 31;
    const int b = blockIdx.z;
    const int bm = blockIdx.y * 128;
    const int bn = blockIdx.x * 128;
    const int wm = wid & 1, wn = wid >> 1;

    const bf16* Ah = Ah_ + (size_t)bm * CCH;                               // proj w
    const bf16* Al = Al_ + (size_t)bm * CCH;
    const bf16* Bh = Bh_ + (size_t)b * HW * CCH + (size_t)bn * CCH;        // attn
    const bf16* Bl = Bl_ + (size_t)b * HW * CCH + (size_t)bn * CCH;

    const int u0row = tid >> 2, u0c = tid & 3;
    const int u1row = (tid + 256) >> 2, u1c = (tid + 256) & 3;

    float acc[4][4][4];
    #pragma unroll
    for (int mi = 0; mi < 4; mi++)
        #pragma unroll
        for (int ni = 0; ni < 4; ni++)
            #pragma unroll
            for (int r = 0; r < 4; r++) acc[mi][ni][r] = 0.f;

    const int g = lane >> 3;
    const int lrow = (g & 1) * 8 + (lane & 7);
    const int lkb  = (g >> 1) * 16;

    auto load_stage = [&](int ks, int buf) {
        const uint32_t base = sb + buf * STAGE_B;
        const int k0 = ks * 32;
        uint32_t so0 = base + u0row * 80 + u0c * 16;
        uint32_t so1 = base + u1row * 80 + u1c * 16;
        size_t ga0 = (size_t)u0row * CCH + k0 + u0c * 8;
        size_t ga1 = (size_t)u1row * CCH + k0 + u1c * 8;
        cp16(so0,              Ah + ga0);
        cp16(so1,              Ah + ga1);
        cp16(so0 + TILE_B,     Al + ga0);
        cp16(so1 + TILE_B,     Al + ga1);
        cp16(so0 + 2 * TILE_B, Bh + ga0);
        cp16(so1 + 2 * TILE_B, Bh + ga1);
        cp16(so0 + 3 * TILE_B, Bl + ga0);
        cp16(so1 + 3 * TILE_B, Bl + ga1);
    };

    load_stage(0, 0);
    asm volatile("cp.async.commit_group;" ::: "memory");

    const int ksteps = CCH / 32;
    for (int ks = 0; ks < ksteps; ks++) {
        const int buf = ks & 1;
        if (ks + 1 < ksteps) {
            load_stage(ks + 1, buf ^ 1);
            asm volatile("cp.async.commit_group;" ::: "memory");
            asm volatile("cp.async.wait_group 1;" ::: "memory");
        } else {
            asm volatile("cp.async.wait_group 0;" ::: "memory");
        }
        __syncthreads();

        const uint32_t base = sb + buf * STAGE_B;
        #pragma unroll
        for (int k16 = 0; k16 < 2; k16++) {
            uint32_t ah[4][4], al[4][4], bh[4][2], bl[4][2];
            #pragma unroll
            for (int mi = 0; mi < 4; mi++) {
                uint32_t ra = base + (wm * 64 + mi * 16 + lrow) * 80 + k16 * 32 + lkb;
                ldsm4(ah[mi][0], ah[mi][1], ah[mi][2], ah[mi][3], ra);
                ldsm4(al[mi][0], al[mi][1], al[mi][2], al[mi][3], ra + TILE_B);
            }
            #pragma unroll
            for (int p = 0; p < 2; p++) {
                uint32_t rb = base + 2 * TILE_B + (wn * 32 + p * 16 + lrow) * 80 + k16 * 32 + lkb;
                uint32_t r0, r1, r2, r3;
                ldsm4(r0, r1, r2, r3, rb);
                bh[2*p][0] = r0; bh[2*p+1][0] = r1; bh[2*p][1] = r2; bh[2*p+1][1] = r3;
                ldsm4(r0, r1, r2, r3, rb + TILE_B);
                bl[2*p][0] = r0; bl[2*p+1][0] = r1; bl[2*p][1] = r2; bl[2*p+1][1] = r3;
            }
            #pragma unroll
            for (int mi = 0; mi < 4; mi++)
                #pragma unroll
                for (int ni = 0; ni < 4; ni++) {
                    mma_bf16(acc[mi][ni], ah[mi], bh[ni]);
                    mma_bf16(acc[mi][ni], ah[mi], bl[ni]);
                    mma_bf16(acc[mi][ni], al[mi], bh[ni]);
                }
        }
        __syncthreads();
    }

    #pragma unroll
    for (int mi = 0; mi < 4; mi++) {
        int r0 = bm + wm * 64 + mi * 16 + (lane >> 2);
        #pragma unroll
        for (int ni = 0; ni < 4; ni++) {
            int col = bn + wn * 32 + ni * 8 + (lane & 3) * 2;
            #pragma unroll
            for (int half = 0; half < 2; half++) {
                int row = r0 + half * 8;
                size_t o = (size_t)b * CCH * HW + (size_t)row * HW + col;
                float bv = bias[row];
                float2 r = *(const float2*)(resid + o);
                *(float2*)(outf + o) = make_float2(acc[mi][ni][half*2] + bv + r.x,
                                                   acc[mi][ni][half*2+1] + bv + r.y);
            }
        }
    }
}

// ---------------- fused flash attention, producer-warp pipelined ----------------
#define QR 128
#define KB 64
#define QSTRIDE 528
#define Q_BYTES (QR * QSTRIDE)            // 67584
#define KV_ROW 528
#define K_BYTES (KB * KV_ROW)             // 33792
#define FA_STAGE (2 * K_BYTES)            // 67584
#define FA_BAR (Q_BYTES + 2 * FA_STAGE)   // 202752
#define FA_SMEM (FA_BAR + 64)

__global__ __launch_bounds__(288, 1)
void flash_attn(const __half* __restrict__ qkvt) {
    extern __shared__ char smem[];
    const uint32_t sb = smem_u32(smem);
    const int tid = threadIdx.x;
    const int wid = tid >> 5, lane = tid & 31;
    const int b = blockIdx.y;
    const int bm = blockIdx.x * QR;
    const __half* base = qkvt + (size_t)b * HW * NQKV;

    const uint32_t sQ = sb;
    const uint32_t sK0 = sb + Q_BYTES;
    const uint32_t BARS = sb + FA_BAR;   // full0 +0, full1 +8, empty0 +16, empty1 +24

    if (tid == 0) {
        MBAR_INIT(BARS + 0, 32u);
        MBAR_INIT(BARS + 8, 32u);
        MBAR_INIT(BARS + 16, 8u);
        MBAR_INIT(BARS + 24, 8u);
    }
    // cooperative Q load: 128 rows x 32 chunks
    for (int u = tid; u < 4096; u += 288) {
        int row = u >> 5, c = u & 31;
        cp16(sQ + row * QSTRIDE + c * 16, base + (size_t)(bm + row) * NQKV + c * 8);
    }
    asm volatile("cp.async.commit_group;" ::: "memory");
    asm volatile("cp.async.wait_group 0;" ::: "memory");
    __syncthreads();

    const int NITER = HW / KB;

    if (wid == 8) {
        // ---- producer warp ----
        for (int ks = 0; ks < NITER; ks++) {
            int buf = ks & 1;
            if (ks >= 2) {
                int par = ((ks >> 1) - 1) & 1;
                MBAR_WAIT(BARS + 16 + buf * 8, par);
            }
            uint32_t st = sK0 + buf * FA_STAGE;
            const __half* gk = base + (size_t)(ks * KB) * NQKV;
            for (int u = lane; u < 2048; u += 32) {
                int row = u >> 5, c = u & 31;
                const __half* gp = gk + (size_t)row * NQKV + c * 8;
                cp16(st + row * KV_ROW + c * 16,           gp + 256);   // K
                cp16(st + K_BYTES + row * KV_ROW + c * 16, gp + 512);   // V
            }
            asm volatile("cp.async.mbarrier.arrive.noinc.shared.b64 [%0];"
                         :: "r"(BARS + buf * 8) : "memory");
        }
        return;
    }

    // ---- consumer warps (wid 0..7; 16 Q rows each) ----
    float O[32][4];
    #pragma unroll
    for (int nt = 0; nt < 32; nt++)
        #pragma unroll
        for (int r = 0; r < 4; r++) O[nt][r] = 0.f;
    float m0 = -1e30f, m1 = -1e30f, l0 = 0.f, l1 = 0.f;

    const int g = lane >> 3;
    const int lrow = (g & 1) * 8 + (lane & 7);
    const int lkb = (g >> 1) * 16;
    const float c1 = 0.0625f * 1.44269504f;

    for (int it = 0; it < NITER; it++) {
        const int buf = it & 1;
        MBAR_WAIT(BARS + buf * 8, (it >> 1) & 1);
        const uint32_t sK = sK0 + buf * FA_STAGE;
        const uint32_t sV = sK + K_BYTES;

        // ---- S = Q K^T : warp tile 16 x 64 ----
        float S[8][4];
        #pragma unroll
        for (int nt = 0; nt < 8; nt++)
            #pragma unroll
            for (int r = 0; r < 4; r++) S[nt][r] = 0.f;

        #pragma unroll
        for (int k16 = 0; k16 < 16; k16++) {
            uint32_t a[4];
            ldsm4(a[0], a[1], a[2], a[3],
                  sQ + (wid * 16 + lrow) * QSTRIDE + k16 * 32 + lkb);
            uint32_t kb[8][2];
            #pragma unroll
            for (int p = 0; p < 4; p++) {
                uint32_t r0, r1, r2, r3;
                ldsm4(r0, r1, r2, r3, sK + (p * 16 + lrow) * KV_ROW + k16 * 32 + lkb);
                kb[2*p][0] = r0; kb[2*p+1][0] = r1;
                kb[2*p][1] = r2; kb[2*p+1][1] = r3;
            }
            #pragma unroll
            for (int nt = 0; nt < 8; nt++)
                mma_f16(S[nt], a, kb[nt]);
        }

        // ---- online softmax ----
        float mx0 = -1e30f, mx1 = -1e30f;
        #pragma unroll
        for (int nt = 0; nt < 8; nt++) {
            mx0 = fmaxf(mx0, fmaxf(S[nt][0], S[nt][1]));
            mx1 = fmaxf(mx1, fmaxf(S[nt][2], S[nt][3]));
        }
        mx0 = fmaxf(mx0, __shfl_xor_sync(0xffffffffu, mx0, 1));
        mx0 = fmaxf(mx0, __shfl_xor_sync(0xffffffffu, mx0, 2));
        mx1 = fmaxf(mx1, __shfl_xor_sync(0xffffffffu, mx1, 1));
        mx1 = fmaxf(mx1, __shfl_xor_sync(0xffffffffu, mx1, 2));
        float nm0 = fmaxf(m0, mx0), nm1 = fmaxf(m1, mx1);
        float a0 = exp2f((m0 - nm0) * c1), a1 = exp2f((m1 - nm1) * c1);
        m0 = nm0; m1 = nm1;
        float rs0 = 0.f, rs1 = 0.f;
        #pragma unroll
        for (int nt = 0; nt < 8; nt++) {
            S[nt][0] = exp2f((S[nt][0] - m0) * c1);
            S[nt][1] = exp2f((S[nt][1] - m0) * c1);
            S[nt][2] = exp2f((S[nt][2] - m1) * c1);
            S[nt][3] = exp2f((S[nt][3] - m1) * c1);
            rs0 += S[nt][0] + S[nt][1];
            rs1 += S[nt][2] + S[nt][3];
        }
        if (!__all_sync(0xffffffffu, (a0 == 1.f) && (a1 == 1.f))) {
            #pragma unroll
            for (int nt = 0; nt < 32; nt++) {
                O[nt][0] *= a0; O[nt][1] *= a0;
                O[nt][2] *= a1; O[nt][3] *= a1;
            }
            l0 *= a0; l1 *= a1;
        }
        l0 += rs0; l1 += rs1;

        // ---- O += P V ----
        #pragma unroll
        for (int k16 = 0; k16 < 4; k16++) {
            uint32_t pa[4];
            __half2 hh;
            hh = __floats2half2_rn(S[2*k16][0],   S[2*k16][1]);   pa[0] = *(uint32_t*)&hh;
            hh = __floats2half2_rn(S[2*k16][2],   S[2*k16][3]);   pa[1] = *(uint32_t*)&hh;
            hh = __floats2half2_rn(S[2*k16+1][0], S[2*k16+1][1]); pa[2] = *(uint32_t*)&hh;
            hh = __floats2half2_rn(S[2*k16+1][2], S[2*k16+1][3]); pa[3] = *(uint32_t*)&hh;
            int krl = k16 * 16 + (g & 1) * 8 + (lane & 7);
            #pragma unroll
            for (int p = 0; p < 16; p++) {
                int ncl = p * 16 + (g >> 1) * 8;
                uint32_t r0, r1, r2, r3;
                ldsm4t(r0, r1, r2, r3, sV + krl * KV_ROW + ncl * 2);
                uint32_t vb0[2] = {r0, r1};
                uint32_t vb1[2] = {r2, r3};
                mma_f16(O[2*p],     pa, vb0);
                mma_f16(O[2*p + 1], pa, vb1);
            }
        }
        // release stage (all ldsm operands consumed by issued mmas)
        if (lane == 0) MBAR_ARRIVE(BARS + 16 + buf * 8);
    }

    // ---- epilogue ----
    l0 += __shfl_xor_sync(0xffffffffu, l0, 1);
    l0 += __shfl_xor_sync(0xffffffffu, l0, 2);
    l1 += __shfl_xor_sync(0xffffffffu, l1, 1);
    l1 += __shfl_xor_sync(0xffffffffu, l1, 2);
    float inv0 = 1.f / l0, inv1 = 1.f / l1;

    bf16* oh = g_at_h + (size_t)b * HW * CCH;
    bf16* ol = g_at_l + (size_t)b * HW * CCH;
    int row0 = bm + wid * 16 + (lane >> 2);
    #pragma unroll
    for (int nt = 0; nt < 32; nt++) {
        int col = nt * 8 + (lane & 3) * 2;
        float v0 = O[nt][0] * inv0, v1 = O[nt][1] * inv0;
        float v2 = O[nt][2] * inv1, v3 = O[nt][3] * inv1;
        bf16 h0, lo0, h1, lo1;
        split2(v0, h0, lo0); split2(v1, h1, lo1);
        size_t o = (size_t)row0 * CCH + col;
        *(__nv_bfloat162*)(oh + o) = __nv_bfloat162(h0, h1);
        *(__nv_bfloat162*)(ol + o) = __nv_bfloat162(lo0, lo1);
        split2(v2, h0, lo0); split2(v3, h1, lo1);
        o = (size_t)(row0 + 8) * CCH + col;
        *(__nv_bfloat162*)(oh + o) = __nv_bfloat162(h0, h1);
        *(__nv_bfloat162*)(ol + o) = __nv_bfloat162(lo0, lo1);
    }
}

// ---------------- launch ----------------
extern "C" void kernel_launch(void* const* d_in, const int* in_sizes, int n_in,
                              void* d_out, int out_size) {
    const float* x     = (const float*)d_in[0];
    const float* gnw   = (const float*)d_in[1];
    const float* gnb   = (const float*)d_in[2];
    const float* qkvw  = (const float*)d_in[3];
    const float* qkvb  = (const float*)d_in[4];
    const float* projw = (const float*)d_in[5];
    const float* projb = (const float*)d_in[6];
    float* out = (float*)d_out;

    __half *qkvt, *xn16, *wq16;
    bf16 *wph, *wpl, *ath, *atl;
    cudaGetSymbolAddress((void**)&qkvt, g_qkvt);
    cudaGetSymbolAddress((void**)&xn16, g_xn16);
    cudaGetSymbolAddress((void**)&wq16, g_wq16);
    cudaGetSymbolAddress((void**)&wph, g_wp_h);
    cudaGetSymbolAddress((void**)&wpl, g_wp_l);
    cudaGetSymbolAddress((void**)&ath, g_at_h);
    cudaGetSymbolAddress((void**)&atl, g_at_l);

    cudaFuncSetAttribute((const void*)hmma_qkv,
                         cudaFuncAttributeMaxDynamicSharedMemorySize, QK_SMEM);
    cudaFuncSetAttribute((const void*)hmma_proj,
                         cudaFuncAttributeMaxDynamicSharedMemorySize, HMMA_SMEM);
    cudaFuncSetAttribute((const void*)flash_attn,
                         cudaFuncAttributeMaxDynamicSharedMemorySize, FA_SMEM);

    // 1. GroupNorm -> fp16 xn^T
    gn_stats<<<BATCH * NGROUPS, 256>>>(x);
    gn_apply_t<<<dim3(HW / 32, CCH / 32, BATCH), dim3(32, 8)>>>(x, gnw, gnb);

    // 2. weight conversions
    w16<<<(NQKV * CCH + 255) / 256, 256>>>(qkvw, wq16, NQKV * CCH);
    w_split<<<(CCH * CCH + 255) / 256, 256>>>(projw, wph, wpl, CCH * CCH);

    // 3. qkv fp16 GEMM: M=4096, N=768, K=256
    hmma_qkv<<<dim3(NQKV / 128, HW / 128, BATCH), 256, QK_SMEM>>>(xn16, wq16, qkvb, qkvt);

    // 4-6. fused flash attention (producer-warp pipelined)
    flash_attn<<<dim3(HW / QR, BATCH), 288, FA_SMEM>>>(qkvt);

    // 7. out = x + W_proj attn + b (bf16x3)
    hmma_proj<<<dim3(HW / 128, CCH / 128, BATCH), 256, HMMA_SMEM>>>(
        wph, wpl, ath, atl, out, projb, x);
}

// round 8
// speedup vs baseline: 5.9597x; 1.0686x over previous
#include <cuda_runtime.h>
#include <cuda_bf16.h>
#include <cuda_fp16.h>
#include <cstdint>

#define BATCH 4
#define CCH 256
#define HW 4096
#define NQKV 768
#define NGROUPS 16
#define EPS 1e-5f

// ---------------- scratch ----------------
__device__ __half g_qkvt[(size_t)BATCH * HW * NQKV];      // 24 MB fp16 [n][q|k|v]
__device__ __half g_xn16[(size_t)BATCH * HW * CCH];       // 8 MB fp16 xn^T [n][c]
__device__ __half g_wq16[NQKV * CCH];                     // fp16 qkv weights
__device__ __half g_wp16[CCH * CCH];                      // fp16 proj weights
__device__ __half g_at16[(size_t)BATCH * HW * CCH];       // fp16 attn [n][c]
__device__ float g_mean[BATCH * NGROUPS];
__device__ float g_rstd[BATCH * NGROUPS];

// ---------------- helpers ----------------
__device__ __forceinline__ uint32_t smem_u32(const void* p) {
    uint32_t a;
    asm("{ .reg .u64 t; cvta.to.shared.u64 t, %1; cvt.u32.u64 %0, t; }" : "=r"(a) : "l"(p));
    return a;
}
__device__ __forceinline__ void cp16(uint32_t s, const void* g) {
    asm volatile("cp.async.cg.shared.global [%0], [%1], 16;" :: "r"(s), "l"(g) : "memory");
}
__device__ __forceinline__ void ldsm4(uint32_t& r0, uint32_t& r1, uint32_t& r2, uint32_t& r3,
                                      uint32_t a) {
    asm volatile("ldmatrix.sync.aligned.m8n8.x4.shared.b16 {%0,%1,%2,%3}, [%4];"
                 : "=r"(r0), "=r"(r1), "=r"(r2), "=r"(r3) : "r"(a));
}
__device__ __forceinline__ void ldsm4t(uint32_t& r0, uint32_t& r1, uint32_t& r2, uint32_t& r3,
                                       uint32_t a) {
    asm volatile("ldmatrix.sync.aligned.m8n8.x4.trans.shared.b16 {%0,%1,%2,%3}, [%4];"
                 : "=r"(r0), "=r"(r1), "=r"(r2), "=r"(r3) : "r"(a));
}
__device__ __forceinline__ void mma_f16(float* c, const uint32_t* a, const uint32_t* b) {
    asm volatile(
        "mma.sync.aligned.m16n8k16.row.col.f32.f16.f16.f32 "
        "{%0,%1,%2,%3}, {%4,%5,%6,%7}, {%8,%9}, {%0,%1,%2,%3};"
        : "+f"(c[0]), "+f"(c[1]), "+f"(c[2]), "+f"(c[3])
        : "r"(a[0]), "r"(a[1]), "r"(a[2]), "r"(a[3]), "r"(b[0]), "r"(b[1]));
}
#define MBAR_INIT(addr, cnt) \
    asm volatile("mbarrier.init.shared.b64 [%0], %1;" :: "r"(addr), "r"(cnt) : "memory")
#define MBAR_ARRIVE(addr) \
    asm volatile("mbarrier.arrive.shared.b64 _, [%0];" :: "r"(addr) : "memory")
#define MBAR_WAIT(addr, phase) do {                                              \
    uint32_t _m = (addr); uint32_t _p = (phase); uint32_t _d;                    \
    asm volatile("{\n\t.reg .pred P;\n\t"                                        \
        "mbarrier.try_wait.parity.acquire.cta.shared::cta.b64 P, [%1], %2;\n\t"  \
        "selp.b32 %0, 1, 0, P;\n\t}" : "=r"(_d) : "r"(_m), "r"(_p) : "memory");  \
    if (!_d) {                                                                   \
        asm volatile("{\n\t.reg .pred P1;\n\t"                                   \
        "W_%=:\n\t"                                                              \
        "mbarrier.try_wait.parity.acquire.cta.shared::cta.b64 P1, [%0], %1, 0x989680;\n\t" \
        "@P1 bra.uni D_%=;\n\tbra.uni W_%=;\n\tD_%=:\n\t}"                       \
        :: "r"(_m), "r"(_p) : "memory");                                         \
    } } while (0)

// ---------------- GroupNorm ----------------
__global__ void gn_stats(const float* __restrict__ x) {
    int bg = blockIdx.x;
    const float4* p = (const float4*)(x + (size_t)bg * 16 * HW);
    float s = 0.f, sq = 0.f;
    for (int i = threadIdx.x; i < 16384; i += 256) {
        float4 v = p[i];
        s  += v.x + v.y + v.z + v.w;
        sq += v.x*v.x + v.y*v.y + v.z*v.z + v.w*v.w;
    }
    __shared__ float ss[256], sz[256];
    ss[threadIdx.x] = s; sz[threadIdx.x] = sq;
    __syncthreads();
    for (int o = 128; o > 0; o >>= 1) {
        if (threadIdx.x < o) { ss[threadIdx.x] += ss[threadIdx.x + o]; sz[threadIdx.x] += sz[threadIdx.x + o]; }
        __syncthreads();
    }
    if (threadIdx.x == 0) {
        float m = ss[0] * (1.f / 65536.f);
        float v = sz[0] * (1.f / 65536.f) - m * m;
        g_mean[bg] = m;
        g_rstd[bg] = rsqrtf(v + EPS);
    }
}

// GroupNorm apply + transpose -> fp16 xn^T [b][n][c]
__global__ void gn_apply_t(const float* __restrict__ x, const float* __restrict__ w,
                           const float* __restrict__ bgn) {
    __shared__ float t[32][33];
    int b = blockIdx.z;
    int n0 = blockIdx.x * 32, c0 = blockIdx.y * 32;
    int tx = threadIdx.x, ty = threadIdx.y;
    const float* src = x + (size_t)b * CCH * HW;
    #pragma unroll
    for (int j = 0; j < 4; j++) {
        int c = c0 + ty + j * 8;
        int bg = b * NGROUPS + (c >> 4);
        float sc = g_rstd[bg] * w[c];
        float sh = bgn[c] - g_mean[bg] * sc;
        t[ty + j * 8][tx] = src[(size_t)c * HW + n0 + tx] * sc + sh;
    }
    __syncthreads();
    __half* d = g_xn16 + (size_t)b * HW * CCH;
    #pragma unroll
    for (int j = 0; j < 4; j++) {
        float v = t[tx][ty + j * 8];
        d[(size_t)(n0 + ty + j * 8) * CCH + c0 + tx] = __float2half_rn(v);
    }
}

// both weight tensors -> fp16 in one launch
__global__ void w16_all(const float* __restrict__ wq, const float* __restrict__ wp) {
    int i = blockIdx.x * 256 + threadIdx.x;
    if (i < NQKV * CCH) g_wq16[i] = __float2half_rn(wq[i]);
    int j = i - NQKV * CCH;
    if (j >= 0 && j < CCH * CCH) g_wp16[j] = __float2half_rn(wp[j]);
}

// ---------------- fp16 GEMM (qkv + proj variants) ----------------
// C[m][n] over A[m][K], B[n][K], K=256 fixed (8 ksteps). 128x128 tile.
// EPI 0 (qkv): out fp16 [row-token][col-out] += bias[col], batch on B? no: A=tokens (batched), B=weights.
// EPI 1 (proj): A=weights (no batch), B=attn tokens (batched), outf fp32 = acc + bias[row] + resid.
#define QK_TILE 10240
#define QK_STAGE 20480
#define QK_SMEM (2 * QK_STAGE)

template<int EPI>
__global__ __launch_bounds__(256, 2)
void hmma_f16gemm(const __half* __restrict__ A_, const __half* __restrict__ B_,
                  const float* __restrict__ bias, __half* __restrict__ outh,
                  float* __restrict__ outf, const float* __restrict__ resid,
                  size_t aB, size_t bB, int ostr, size_t oB) {
    extern __shared__ char smem[];
    const uint32_t sb = smem_u32(smem);
    const int tid = threadIdx.x;
    const int wid = tid >> 5, lane = tid & 31;
    const int b = blockIdx.z;
    const int bm = blockIdx.y * 128;
    const int bn = blockIdx.x * 128;
    const int wm = wid & 1, wn = wid >> 1;

    const __half* A = A_ + (size_t)b * aB + (size_t)bm * CCH;
    const __half* B = B_ + (size_t)b * bB + (size_t)bn * CCH;

    const int u0row = tid >> 2, u0c = tid & 3;
    const int u1row = (tid + 256) >> 2, u1c = (tid + 256) & 3;

    float acc[4][4][4];
    #pragma unroll
    for (int mi = 0; mi < 4; mi++)
        #pragma unroll
        for (int ni = 0; ni < 4; ni++)
            #pragma unroll
            for (int r = 0; r < 4; r++) acc[mi][ni][r] = 0.f;

    const int g = lane >> 3;
    const int lrow = (g & 1) * 8 + (lane & 7);
    const int lkb  = (g >> 1) * 16;

    auto load_stage = [&](int ks, int buf) {
        const uint32_t base = sb + buf * QK_STAGE;
        const int k0 = ks * 32;
        uint32_t so0 = base + u0row * 80 + u0c * 16;
        uint32_t so1 = base + u1row * 80 + u1c * 16;
        cp16(so0,           A + (size_t)u0row * CCH + k0 + u0c * 8);
        cp16(so1,           A + (size_t)u1row * CCH + k0 + u1c * 8);
        cp16(so0 + QK_TILE, B + (size_t)u0row * CCH + k0 + u0c * 8);
        cp16(so1 + QK_TILE, B + (size_t)u1row * CCH + k0 + u1c * 8);
    };

    load_stage(0, 0);
    asm volatile("cp.async.commit_group;" ::: "memory");

    const int ksteps = CCH / 32;
    for (int ks = 0; ks < ksteps; ks++) {
        const int buf = ks & 1;
        if (ks + 1 < ksteps) {
            load_stage(ks + 1, buf ^ 1);
            asm volatile("cp.async.commit_group;" ::: "memory");
            asm volatile("cp.async.wait_group 1;" ::: "memory");
        } else {
            asm volatile("cp.async.wait_group 0;" ::: "memory");
        }
        __syncthreads();

        const uint32_t base = sb + buf * QK_STAGE;
        #pragma unroll
        for (int k16 = 0; k16 < 2; k16++) {
            uint32_t ah[4][4], bh[4][2];
            #pragma unroll
            for (int mi = 0; mi < 4; mi++) {
                uint32_t ra = base + (wm * 64 + mi * 16 + lrow) * 80 + k16 * 32 + lkb;
                ldsm4(ah[mi][0], ah[mi][1], ah[mi][2], ah[mi][3], ra);
            }
            #pragma unroll
            for (int p = 0; p < 2; p++) {
                uint32_t rb = base + QK_TILE + (wn * 32 + p * 16 + lrow) * 80 + k16 * 32 + lkb;
                uint32_t r0, r1, r2, r3;
                ldsm4(r0, r1, r2, r3, rb);
                bh[2*p][0] = r0; bh[2*p+1][0] = r1; bh[2*p][1] = r2; bh[2*p+1][1] = r3;
            }
            #pragma unroll
            for (int mi = 0; mi < 4; mi++)
                #pragma unroll
                for (int ni = 0; ni < 4; ni++)
                    mma_f16(acc[mi][ni], ah[mi], bh[ni]);
        }
        __syncthreads();
    }

    #pragma unroll
    for (int mi = 0; mi < 4; mi++) {
        int r0 = bm + wm * 64 + mi * 16 + (lane >> 2);
        #pragma unroll
        for (int ni = 0; ni < 4; ni++) {
            int col = bn + wn * 32 + ni * 8 + (lane & 3) * 2;
            #pragma unroll
            for (int half = 0; half < 2; half++) {
                int row = r0 + half * 8;
                float v0 = acc[mi][ni][half * 2 + 0];
                float v1 = acc[mi][ni][half * 2 + 1];
                if (EPI == 0) {
                    v0 += bias[col]; v1 += bias[col + 1];
                    *(__half2*)(outh + (size_t)b * oB + (size_t)row * ostr + col) =
                        __floats2half2_rn(v0, v1);
                } else {
                    // out[row=out_ch][col=token]: bias[row] + resid
                    size_t o = (size_t)b * oB + (size_t)row * ostr + col;
                    float bv = bias[row];
                    float2 r = *(const float2*)(resid + o);
                    *(float2*)(outf + o) = make_float2(v0 + bv + r.x, v1 + bv + r.y);
                }
            }
        }
    }
}

// ---------------- fused flash attention, producer-warp pipelined ----------------
#define QR 128
#define KB 64
#define QSTRIDE 528
#define Q_BYTES (QR * QSTRIDE)            // 67584
#define KV_ROW 528
#define K_BYTES (KB * KV_ROW)             // 33792
#define FA_STAGE (2 * K_BYTES)            // 67584
#define FA_BAR (Q_BYTES + 2 * FA_STAGE)   // 202752
#define FA_SMEM (FA_BAR + 64)

__global__ __launch_bounds__(288, 1)
void flash_attn(const __half* __restrict__ qkvt) {
    extern __shared__ char smem[];
    const uint32_t sb = smem_u32(smem);
    const int tid = threadIdx.x;
    const int wid = tid >> 5, lane = tid & 31;
    const int b = blockIdx.y;
    const int bm = blockIdx.x * QR;
    const __half* base = qkvt + (size_t)b * HW * NQKV;

    const uint32_t sQ = sb;
    const uint32_t sK0 = sb + Q_BYTES;
    const uint32_t BARS = sb + FA_BAR;   // full0 +0, full1 +8, empty0 +16, empty1 +24

    if (tid == 0) {
        MBAR_INIT(BARS + 0, 32u);
        MBAR_INIT(BARS + 8, 32u);
        MBAR_INIT(BARS + 16, 8u);
        MBAR_INIT(BARS + 24, 8u);
    }
    for (int u = tid; u < 4096; u += 288) {
        int row = u >> 5, c = u & 31;
        cp16(sQ + row * QSTRIDE + c * 16, base + (size_t)(bm + row) * NQKV + c * 8);
    }
    asm volatile("cp.async.commit_group;" ::: "memory");
    asm volatile("cp.async.wait_group 0;" ::: "memory");
    __syncthreads();

    const int NITER = HW / KB;

    if (wid == 8) {
        for (int ks = 0; ks < NITER; ks++) {
            int buf = ks & 1;
            if (ks >= 2) {
                int par = ((ks >> 1) - 1) & 1;
                MBAR_WAIT(BARS + 16 + buf * 8, par);
            }
            uint32_t st = sK0 + buf * FA_STAGE;
            const __half* gk = base + (size_t)(ks * KB) * NQKV;
            for (int u = lane; u < 2048; u += 32) {
                int row = u >> 5, c = u & 31;
                const __half* gp = gk + (size_t)row * NQKV + c * 8;
                cp16(st + row * KV_ROW + c * 16,           gp + 256);   // K
                cp16(st + K_BYTES + row * KV_ROW + c * 16, gp + 512);   // V
            }
            asm volatile("cp.async.mbarrier.arrive.noinc.shared.b64 [%0];"
                         :: "r"(BARS + buf * 8) : "memory");
        }
        return;
    }

    float O[32][4];
    #pragma unroll
    for (int nt = 0; nt < 32; nt++)
        #pragma unroll
        for (int r = 0; r < 4; r++) O[nt][r] = 0.f;
    float m0 = -1e30f, m1 = -1e30f, l0 = 0.f, l1 = 0.f;

    const int g = lane >> 3;
    const int lrow = (g & 1) * 8 + (lane & 7);
    const int lkb = (g >> 1) * 16;
    const float c1 = 0.0625f * 1.44269504f;

    for (int it = 0; it < NITER; it++) {
        const int buf = it & 1;
        MBAR_WAIT(BARS + buf * 8, (it >> 1) & 1);
        const uint32_t sK = sK0 + buf * FA_STAGE;
        const uint32_t sV = sK + K_BYTES;

        float S[8][4];
        #pragma unroll
        for (int nt = 0; nt < 8; nt++)
            #pragma unroll
            for (int r = 0; r < 4; r++) S[nt][r] = 0.f;

        #pragma unroll
        for (int k16 = 0; k16 < 16; k16++) {
            uint32_t a[4];
            ldsm4(a[0], a[1], a[2], a[3],
                  sQ + (wid * 16 + lrow) * QSTRIDE + k16 * 32 + lkb);
            uint32_t kb[8][2];
            #pragma unroll
            for (int p = 0; p < 4; p++) {
                uint32_t r0, r1, r2, r3;
                ldsm4(r0, r1, r2, r3, sK + (p * 16 + lrow) * KV_ROW + k16 * 32 + lkb);
                kb[2*p][0] = r0; kb[2*p+1][0] = r1;
                kb[2*p][1] = r2; kb[2*p+1][1] = r3;
            }
            #pragma unroll
            for (int nt = 0; nt < 8; nt++)
                mma_f16(S[nt], a, kb[nt]);
        }

        float mx0 = -1e30f, mx1 = -1e30f;
        #pragma unroll
        for (int nt = 0; nt < 8; nt++) {
            mx0 = fmaxf(mx0, fmaxf(S[nt][0], S[nt][1]));
            mx1 = fmaxf(mx1, fmaxf(S[nt][2], S[nt][3]));
        }
        mx0 = fmaxf(mx0, __shfl_xor_sync(0xffffffffu, mx0, 1));
        mx0 = fmaxf(mx0, __shfl_xor_sync(0xffffffffu, mx0, 2));
        mx1 = fmaxf(mx1, __shfl_xor_sync(0xffffffffu, mx1, 1));
        mx1 = fmaxf(mx1, __shfl_xor_sync(0xffffffffu, mx1, 2));
        float nm0 = fmaxf(m0, mx0), nm1 = fmaxf(m1, mx1);
        float a0 = exp2f((m0 - nm0) * c1), a1 = exp2f((m1 - nm1) * c1);
        m0 = nm0; m1 = nm1;
        float rs0 = 0.f, rs1 = 0.f;
        #pragma unroll
        for (int nt = 0; nt < 8; nt++) {
            S[nt][0] = exp2f((S[nt][0] - m0) * c1);
            S[nt][1] = exp2f((S[nt][1] - m0) * c1);
            S[nt][2] = exp2f((S[nt][2] - m1) * c1);
            S[nt][3] = exp2f((S[nt][3] - m1) * c1);
            rs0 += S[nt][0] + S[nt][1];
            rs1 += S[nt][2] + S[nt][3];
        }
        if (!__all_sync(0xffffffffu, (a0 == 1.f) && (a1 == 1.f))) {
            #pragma unroll
            for (int nt = 0; nt < 32; nt++) {
                O[nt][0] *= a0; O[nt][1] *= a0;
                O[nt][2] *= a1; O[nt][3] *= a1;
            }
            l0 *= a0; l1 *= a1;
        }
        l0 += rs0; l1 += rs1;

        #pragma unroll
        for (int k16 = 0; k16 < 4; k16++) {
            uint32_t pa[4];
            __half2 hh;
            hh = __floats2half2_rn(S[2*k16][0],   S[2*k16][1]);   pa[0] = *(uint32_t*)&hh;
            hh = __floats2half2_rn(S[2*k16][2],   S[2*k16][3]);   pa[1] = *(uint32_t*)&hh;
            hh = __floats2half2_rn(S[2*k16+1][0], S[2*k16+1][1]); pa[2] = *(uint32_t*)&hh;
            hh = __floats2half2_rn(S[2*k16+1][2], S[2*k16+1][3]); pa[3] = *(uint32_t*)&hh;
            int krl = k16 * 16 + (g & 1) * 8 + (lane & 7);
            #pragma unroll
            for (int p = 0; p < 16; p++) {
                int ncl = p * 16 + (g >> 1) * 8;
                uint32_t r0, r1, r2, r3;
                ldsm4t(r0, r1, r2, r3, sV + krl * KV_ROW + ncl * 2);
                uint32_t vb0[2] = {r0, r1};
                uint32_t vb1[2] = {r2, r3};
                mma_f16(O[2*p],     pa, vb0);
                mma_f16(O[2*p + 1], pa, vb1);
            }
        }
        if (lane == 0) MBAR_ARRIVE(BARS + 16 + buf * 8);
    }

    // ---- epilogue: normalize -> fp16 attn ----
    l0 += __shfl_xor_sync(0xffffffffu, l0, 1);
    l0 += __shfl_xor_sync(0xffffffffu, l0, 2);
    l1 += __shfl_xor_sync(0xffffffffu, l1, 1);
    l1 += __shfl_xor_sync(0xffffffffu, l1, 2);
    float inv0 = 1.f / l0, inv1 = 1.f / l1;

    __half* oa = g_at16 + (size_t)b * HW * CCH;
    int row0 = bm + wid * 16 + (lane >> 2);
    #pragma unroll
    for (int nt = 0; nt < 32; nt++) {
        int col = nt * 8 + (lane & 3) * 2;
        *(__half2*)(oa + (size_t)row0 * CCH + col) =
            __floats2half2_rn(O[nt][0] * inv0, O[nt][1] * inv0);
        *(__half2*)(oa + (size_t)(row0 + 8) * CCH + col) =
            __floats2half2_rn(O[nt][2] * inv1, O[nt][3] * inv1);
    }
}

// ---------------- launch ----------------
extern "C" void kernel_launch(void* const* d_in, const int* in_sizes, int n_in,
                              void* d_out, int out_size) {
    const float* x     = (const float*)d_in[0];
    const float* gnw   = (const float*)d_in[1];
    const float* gnb   = (const float*)d_in[2];
    const float* qkvw  = (const float*)d_in[3];
    const float* qkvb  = (const float*)d_in[4];
    const float* projw = (const float*)d_in[5];
    const float* projb = (const float*)d_in[6];
    float* out = (float*)d_out;

    __half *qkvt, *xn16, *wq16, *wp16, *at16;
    cudaGetSymbolAddress((void**)&qkvt, g_qkvt);
    cudaGetSymbolAddress((void**)&xn16, g_xn16);
    cudaGetSymbolAddress((void**)&wq16, g_wq16);
    cudaGetSymbolAddress((void**)&wp16, g_wp16);
    cudaGetSymbolAddress((void**)&at16, g_at16);

    cudaFuncSetAttribute((const void*)hmma_f16gemm<0>,
                         cudaFuncAttributeMaxDynamicSharedMemorySize, QK_SMEM);
    cudaFuncSetAttribute((const void*)hmma_f16gemm<1>,
                         cudaFuncAttributeMaxDynamicSharedMemorySize, QK_SMEM);
    cudaFuncSetAttribute((const void*)flash_attn,
                         cudaFuncAttributeMaxDynamicSharedMemorySize, FA_SMEM);

    // 1. GroupNorm -> fp16 xn^T
    gn_stats<<<BATCH * NGROUPS, 256>>>(x);
    gn_apply_t<<<dim3(HW / 32, CCH / 32, BATCH), dim3(32, 8)>>>(x, gnw, gnb);

    // 2. weight conversions (one launch)
    w16_all<<<(NQKV * CCH + CCH * CCH + 255) / 256, 256>>>(qkvw, projw);

    // 3. qkv fp16 GEMM: A=xn tokens (batched), B=Wq. out fp16 qkvt.
    hmma_f16gemm<0><<<dim3(NQKV / 128, HW / 128, BATCH), 256, QK_SMEM>>>(
        xn16, wq16, qkvb, qkvt, nullptr, nullptr,
        (size_t)HW * CCH, 0, NQKV, (size_t)HW * NQKV);

    // 4-6. fused flash attention -> fp16 attn
    flash_attn<<<dim3(HW / QR, BATCH), 288, FA_SMEM>>>(qkvt);

    // 7. proj fp16: A=Wp (no batch), B=attn tokens (batched). out fp32 = acc+bias[row]+x.
    hmma_f16gemm<1><<<dim3(HW / 128, CCH / 128, BATCH), 256, QK_SMEM>>>(
        wp16, at16, projb, nullptr, out, x,
        0, (size_t)HW * CCH, HW, (size_t)CCH * HW);
}